// round 1
// baseline (speedup 1.0000x reference)
#include <cuda_runtime.h>
#include <math.h>

#define B_   2
#define S_   2048
#define HID_ 1024
#define NH_  16
#define HD_  64
#define MTOT (B_ * S_)   // 4096

// ---------------------------------------------------------------------------
// Scratch (no cudaMalloc allowed): Q, K, V projections and attention output.
// ---------------------------------------------------------------------------
__device__ float g_q[MTOT * HID_];
__device__ float g_k[MTOT * HID_];
__device__ float g_v[MTOT * HID_];
__device__ float g_attn[MTOT * HID_];

// ---------------------------------------------------------------------------
// SGEMM:  C[M,N] = A[M,K] @ W[N,K]^T + bias[N]
// 128x128 block tile, BK=8, 256 threads, 8x8 per-thread microtile.
// blockIdx.z selects among up to 3 (W, bias, C) sets (fused QKV).
// M, N, K assumed multiples of tile sizes (4096/1024/1024 here).
// ---------------------------------------------------------------------------
__global__ void __launch_bounds__(256)
gemm_bias_kernel(const float* __restrict__ A,
                 const float* __restrict__ W0, const float* __restrict__ W1,
                 const float* __restrict__ W2,
                 const float* __restrict__ b0, const float* __restrict__ b1,
                 const float* __restrict__ b2,
                 float* __restrict__ C0, float* __restrict__ C1,
                 float* __restrict__ C2,
                 int M, int N, int K)
{
    constexpr int BM = 128, BN = 128, BK = 8, TM = 8, TN = 8;

    const float* W;
    const float* bias;
    float* C;
    if (blockIdx.z == 0)      { W = W0; bias = b0; C = C0; }
    else if (blockIdx.z == 1) { W = W1; bias = b1; C = C1; }
    else                      { W = W2; bias = b2; C = C2; }

    __shared__ float As[BK][BM];
    __shared__ float Ws[BK][BN];

    const int tid = threadIdx.x;          // 0..255
    const int lr  = tid >> 1;             // 0..127 (load row)
    const int lc  = (tid & 1) * 4;        // 0 or 4 (load col, float4)
    const int tr  = (tid >> 4) * TM;      // compute row base
    const int tc  = (tid & 15) * TN;      // compute col base

    const float* Ap = A + (size_t)(blockIdx.y * BM + lr) * K + lc;
    const float* Wp = W + (size_t)(blockIdx.x * BN + lr) * K + lc;

    float acc[TM][TN];
    #pragma unroll
    for (int i = 0; i < TM; i++)
        #pragma unroll
        for (int j = 0; j < TN; j++)
            acc[i][j] = 0.0f;

    for (int k0 = 0; k0 < K; k0 += BK) {
        float4 a4 = *(const float4*)(Ap + k0);
        float4 w4 = *(const float4*)(Wp + k0);
        As[lc + 0][lr] = a4.x; As[lc + 1][lr] = a4.y;
        As[lc + 2][lr] = a4.z; As[lc + 3][lr] = a4.w;
        Ws[lc + 0][lr] = w4.x; Ws[lc + 1][lr] = w4.y;
        Ws[lc + 2][lr] = w4.z; Ws[lc + 3][lr] = w4.w;
        __syncthreads();

        #pragma unroll
        for (int kk = 0; kk < BK; kk++) {
            float ra[TM], rb[TN];
            *(float4*)&ra[0] = *(const float4*)&As[kk][tr];
            *(float4*)&ra[4] = *(const float4*)&As[kk][tr + 4];
            *(float4*)&rb[0] = *(const float4*)&Ws[kk][tc];
            *(float4*)&rb[4] = *(const float4*)&Ws[kk][tc + 4];
            #pragma unroll
            for (int i = 0; i < TM; i++)
                #pragma unroll
                for (int j = 0; j < TN; j++)
                    acc[i][j] = fmaf(ra[i], rb[j], acc[i][j]);
        }
        __syncthreads();
    }

    // epilogue: add bias, store
    float bb[TN];
    *(float4*)&bb[0] = *(const float4*)(bias + blockIdx.x * BN + tc);
    *(float4*)&bb[4] = *(const float4*)(bias + blockIdx.x * BN + tc + 4);

    #pragma unroll
    for (int i = 0; i < TM; i++) {
        float* Crow = C + (size_t)(blockIdx.y * BM + tr + i) * N + blockIdx.x * BN + tc;
        float4 o0, o1;
        o0.x = acc[i][0] + bb[0]; o0.y = acc[i][1] + bb[1];
        o0.z = acc[i][2] + bb[2]; o0.w = acc[i][3] + bb[3];
        o1.x = acc[i][4] + bb[4]; o1.y = acc[i][5] + bb[5];
        o1.z = acc[i][6] + bb[6]; o1.w = acc[i][7] + bb[7];
        *(float4*)(Crow)     = o0;
        *(float4*)(Crow + 4) = o1;
    }
}

// ---------------------------------------------------------------------------
// Flash-attention fp32: one block = 64 queries of one (b, h); loops over key
// tiles of 64. Online softmax. 256 threads, 16x16 layout, 4x4 microtiles.
// smem (dynamic, padded stride 68 for conflict avoidance):
//   Qt [HD][68]  : Q transposed   (d-major)
//   KP [64][68]  : K transposed (d-major), then reused for P^T (c-major)
//   Vs [64][68]  : V natural      (c-major)
// ---------------------------------------------------------------------------
#define ATTN_PAD   68
#define ATTN_SMEM  (3 * 64 * ATTN_PAD * 4)

__global__ void __launch_bounds__(256)
attn_kernel(const float* __restrict__ Q, const float* __restrict__ Kg_,
            const float* __restrict__ Vg_, float* __restrict__ O)
{
    extern __shared__ float sm[];
    float* Qt = sm;                      // [64][68]
    float* KP = sm + 64 * ATTN_PAD;      // [64][68]
    float* Vs = sm + 2 * 64 * ATTN_PAD;  // [64][68]

    const int tid = threadIdx.x;
    const int tx  = tid & 15;            // 0..15 -> score cols / out cols
    const int ty  = tid >> 4;            // 0..15 -> rows
    const int bh  = blockIdx.y;
    const int b   = bh / NH_;
    const int h   = bh % NH_;
    const int q0  = blockIdx.x * 64;

    const float* Qg = Q   + ((size_t)(b * S_ + q0)) * HID_ + h * HD_;
    const float* Kg = Kg_ + ((size_t)b * S_) * HID_ + h * HD_;
    const float* Vg = Vg_ + ((size_t)b * S_) * HID_ + h * HD_;

    // ---- load Q tile transposed: Qt[d][r] = Q[q0+r][d] ----
    {
        const int r  = tid >> 2;             // 0..63
        const int c0 = (tid & 3) * 16;       // 0,16,32,48
        const float4* src = (const float4*)(Qg + (size_t)r * HID_ + c0);
        #pragma unroll
        for (int i = 0; i < 4; i++) {
            float4 v = src[i];
            int d = c0 + 4 * i;
            Qt[(d + 0) * ATTN_PAD + r] = v.x;
            Qt[(d + 1) * ATTN_PAD + r] = v.y;
            Qt[(d + 2) * ATTN_PAD + r] = v.z;
            Qt[(d + 3) * ATTN_PAD + r] = v.w;
        }
    }

    float m[4], l[4], acc[4][4];
    #pragma unroll
    for (int i = 0; i < 4; i++) {
        m[i] = -1e30f; l[i] = 0.0f;
        #pragma unroll
        for (int j = 0; j < 4; j++) acc[i][j] = 0.0f;
    }

    const float SCALE = 0.125f;  // 1/sqrt(64)
    __syncthreads();

    for (int kt = 0; kt < S_; kt += 64) {
        // ---- load K tile transposed + V tile natural ----
        {
            const int r  = tid >> 2;
            const int c0 = (tid & 3) * 16;
            const float4* ks = (const float4*)(Kg + (size_t)(kt + r) * HID_ + c0);
            #pragma unroll
            for (int i = 0; i < 4; i++) {
                float4 v = ks[i];
                int d = c0 + 4 * i;
                KP[(d + 0) * ATTN_PAD + r] = v.x;
                KP[(d + 1) * ATTN_PAD + r] = v.y;
                KP[(d + 2) * ATTN_PAD + r] = v.z;
                KP[(d + 3) * ATTN_PAD + r] = v.w;
            }
            const float4* vsrc = (const float4*)(Vg + (size_t)(kt + r) * HID_ + c0);
            float4* vdst = (float4*)(Vs + (size_t)r * ATTN_PAD + c0);
            #pragma unroll
            for (int i = 0; i < 4; i++) vdst[i] = vsrc[i];
        }
        __syncthreads();

        // ---- scores: s[i][j] = sum_d Q[4ty+i][d] * K[4tx+j][d] ----
        float s[4][4];
        #pragma unroll
        for (int i = 0; i < 4; i++)
            #pragma unroll
            for (int j = 0; j < 4; j++) s[i][j] = 0.0f;

        #pragma unroll 8
        for (int k = 0; k < HD_; k++) {
            float4 q4 = *(const float4*)(Qt + k * ATTN_PAD + 4 * ty);
            float4 k4 = *(const float4*)(KP + k * ATTN_PAD + 4 * tx);
            float qa[4] = {q4.x, q4.y, q4.z, q4.w};
            float kb[4] = {k4.x, k4.y, k4.z, k4.w};
            #pragma unroll
            for (int i = 0; i < 4; i++)
                #pragma unroll
                for (int j = 0; j < 4; j++)
                    s[i][j] = fmaf(qa[i], kb[j], s[i][j]);
        }

        // ---- online softmax update ----
        float p[4][4];
        #pragma unroll
        for (int i = 0; i < 4; i++) {
            #pragma unroll
            for (int j = 0; j < 4; j++) s[i][j] *= SCALE;

            float mt = fmaxf(fmaxf(s[i][0], s[i][1]), fmaxf(s[i][2], s[i][3]));
            #pragma unroll
            for (int off = 8; off >= 1; off >>= 1)
                mt = fmaxf(mt, __shfl_xor_sync(0xffffffffu, mt, off, 16));

            float mnew = fmaxf(m[i], mt);
            float corr = __expf(m[i] - mnew);
            m[i] = mnew;
            l[i] *= corr;
            #pragma unroll
            for (int j = 0; j < 4; j++) acc[i][j] *= corr;

            float lt = 0.0f;
            #pragma unroll
            for (int j = 0; j < 4; j++) {
                p[i][j] = __expf(s[i][j] - mnew);
                lt += p[i][j];
            }
            #pragma unroll
            for (int off = 8; off >= 1; off >>= 1)
                lt += __shfl_xor_sync(0xffffffffu, lt, off, 16);
            l[i] += lt;
        }

        __syncthreads();  // everyone done reading KP as K^T

        // ---- write P^T into KP: KP[c][r] = p ----
        #pragma unroll
        for (int j = 0; j < 4; j++)
            #pragma unroll
            for (int i = 0; i < 4; i++)
                KP[(4 * tx + j) * ATTN_PAD + 4 * ty + i] = p[i][j];
        __syncthreads();

        // ---- O += P @ V : acc[i][j] += sum_c P[r][c] * V[c][d] ----
        #pragma unroll 8
        for (int c = 0; c < 64; c++) {
            float4 p4 = *(const float4*)(KP + c * ATTN_PAD + 4 * ty);
            float4 v4 = *(const float4*)(Vs + c * ATTN_PAD + 4 * tx);
            float pa[4] = {p4.x, p4.y, p4.z, p4.w};
            float vb[4] = {v4.x, v4.y, v4.z, v4.w};
            #pragma unroll
            for (int i = 0; i < 4; i++)
                #pragma unroll
                for (int j = 0; j < 4; j++)
                    acc[i][j] = fmaf(pa[i], vb[j], acc[i][j]);
        }
        __syncthreads();  // before next tile overwrites KP / Vs
    }

    // ---- normalize + store (concat-heads layout [B,S,HID]) ----
    #pragma unroll
    for (int i = 0; i < 4; i++) {
        float inv = 1.0f / l[i];
        float4 o;
        o.x = acc[i][0] * inv; o.y = acc[i][1] * inv;
        o.z = acc[i][2] * inv; o.w = acc[i][3] * inv;
        *(float4*)(O + (size_t)(b * S_ + q0 + 4 * ty + i) * HID_ + h * HD_ + 4 * tx) = o;
    }
}

// ---------------------------------------------------------------------------
// Launch
// ---------------------------------------------------------------------------
extern "C" void kernel_launch(void* const* d_in, const int* in_sizes, int n_in,
                              void* d_out, int out_size)
{
    const float* x  = (const float*)d_in[0];
    const float* Wq = (const float*)d_in[1];
    const float* bq = (const float*)d_in[2];
    const float* Wk = (const float*)d_in[3];
    const float* bk = (const float*)d_in[4];
    const float* Wv = (const float*)d_in[5];
    const float* bv = (const float*)d_in[6];
    const float* Wo = (const float*)d_in[7];
    const float* bo = (const float*)d_in[8];
    float* out = (float*)d_out;

    float *qp, *kp, *vp, *ap;
    cudaGetSymbolAddress((void**)&qp, g_q);
    cudaGetSymbolAddress((void**)&kp, g_k);
    cudaGetSymbolAddress((void**)&vp, g_v);
    cudaGetSymbolAddress((void**)&ap, g_attn);

    // 1) fused QKV projections
    {
        dim3 grid(HID_ / 128, MTOT / 128, 3);
        gemm_bias_kernel<<<grid, 256>>>(x, Wq, Wk, Wv, bq, bk, bv,
                                        qp, kp, vp, MTOT, HID_, HID_);
    }

    // 2) attention
    {
        cudaFuncSetAttribute(attn_kernel,
                             cudaFuncAttributeMaxDynamicSharedMemorySize,
                             ATTN_SMEM);
        dim3 grid(S_ / 64, B_ * NH_);
        attn_kernel<<<grid, 256, ATTN_SMEM>>>(qp, kp, vp, ap);
    }

    // 3) output projection
    {
        dim3 grid(HID_ / 128, MTOT / 128, 1);
        gemm_bias_kernel<<<grid, 256>>>(ap, Wo, Wo, Wo, bo, bo, bo,
                                        out, out, out, MTOT, HID_, HID_);
    }
}

// round 3
// speedup vs baseline: 1.3799x; 1.3799x over previous
#include <cuda_runtime.h>
#include <cstdint>
#include <math.h>

#define B_   2
#define S_   2048
#define HID_ 1024
#define NH_  16
#define HD_  64
#define MTOT (B_ * S_)   // 4096

// ---------------------------------------------------------------------------
// Scratch buffers (no cudaMalloc allowed)
// ---------------------------------------------------------------------------
__device__ float g_q[MTOT * HID_];
__device__ float g_k[MTOT * HID_];
__device__ float g_v[MTOT * HID_];
__device__ float g_attn[MTOT * HID_];

// ---------------------------------------------------------------------------
// Helpers
// ---------------------------------------------------------------------------
__device__ __forceinline__ uint32_t smem_u32(const void* p) {
    uint32_t a;
    asm("{ .reg .u64 t; cvta.to.shared.u64 t, %1; cvt.u32.u64 %0, t; }"
        : "=r"(a) : "l"(p));
    return a;
}

__device__ __forceinline__ float to_tf32(float x) {
    uint32_t o;
    asm("cvt.rna.tf32.f32 %0, %1;" : "=r"(o) : "f"(x));
    return __uint_as_float(o);
}

__device__ __forceinline__ void ldmatrix_x4(uint32_t& r0, uint32_t& r1,
                                            uint32_t& r2, uint32_t& r3,
                                            uint32_t addr) {
    asm volatile("ldmatrix.sync.aligned.m8n8.x4.shared.b16 {%0,%1,%2,%3}, [%4];"
                 : "=r"(r0), "=r"(r1), "=r"(r2), "=r"(r3) : "r"(addr));
}

__device__ __forceinline__ void mma_tf32(float& c0, float& c1, float& c2, float& c3,
                                         uint32_t a0, uint32_t a1, uint32_t a2,
                                         uint32_t a3, uint32_t b0, uint32_t b1) {
    asm volatile(
        "mma.sync.aligned.m16n8k8.row.col.f32.tf32.tf32.f32 "
        "{%0,%1,%2,%3}, {%4,%5,%6,%7}, {%8,%9}, {%0,%1,%2,%3};"
        : "+f"(c0), "+f"(c1), "+f"(c2), "+f"(c3)
        : "r"(a0), "r"(a1), "r"(a2), "r"(a3), "r"(b0), "r"(b1));
}

// ---------------------------------------------------------------------------
// tf32 mma.sync GEMM:  C[M,N] = A[M,K] @ W[N,K]^T + bias[N]
// 128x128x32 CTA tile, 256 threads (8 warps: 4 x 2), 32x64 warp tile,
// double-buffered smem (pitch 36 floats), ldmatrix.x4 fragment loads.
// blockIdx.z selects among 3 (W, bias, C) sets (fused QKV).
// ---------------------------------------------------------------------------
#define GPITCH 36                       // floats per smem row (conflict-free)
#define GTILE_F (128 * GPITCH)          // floats per tile (A or B)
#define GEMM_SMEM (4 * GTILE_F * 4)     // 2 buffers x 2 tiles

__global__ void __launch_bounds__(256)
gemm_tc(const float* __restrict__ A,
        const float* __restrict__ W0, const float* __restrict__ W1,
        const float* __restrict__ W2,
        const float* __restrict__ b0_, const float* __restrict__ b1_,
        const float* __restrict__ b2_,
        float* __restrict__ C0, float* __restrict__ C1, float* __restrict__ C2,
        int M, int N, int K)
{
    extern __shared__ float smf[];
    const int tid  = threadIdx.x;
    const int wid  = tid >> 5;
    const int lane = tid & 31;
    const int warpM = wid & 3;          // 0..3 -> rows
    const int warpN = wid >> 2;         // 0..1 -> cols

    const float* W; const float* bias; float* C;
    if (blockIdx.z == 0)      { W = W0; bias = b0_; C = C0; }
    else if (blockIdx.z == 1) { W = W1; bias = b1_; C = C1; }
    else                      { W = W2; bias = b2_; C = C2; }

    // smem layout: [buf][A(4608f), B(4608f)]
    float* sA[2] = { smf,               smf + 2 * GTILE_F };
    float* sB[2] = { smf + GTILE_F,     smf + 3 * GTILE_F };

    const int rowM = blockIdx.y * 128;
    const int colN = blockIdx.x * 128;
    const float* Ag = A + (size_t)rowM * K;
    const float* Wg = W + (size_t)colN * K;

    // global-load mapping: 4 rows per tile per thread, float4 columns
    const int gr = tid >> 3;            // 0..31
    const int gc = (tid & 7) * 4;       // 0..28

    // ldmatrix per-lane offsets
    const int a_row = ((lane >> 3) & 1) * 8 + (lane & 7);
    const int a_kq  = ((lane >> 4) & 1) * 4;
    const int b_row = ((lane >> 4) & 1) * 8 + (lane & 7);
    const int b_kq  = ((lane >> 3) & 1) * 4;

    const uint32_t sbA[2] = { smem_u32(sA[0]), smem_u32(sA[1]) };
    const uint32_t sbB[2] = { smem_u32(sB[0]), smem_u32(sB[1]) };

    float acc[2][8][4];
    #pragma unroll
    for (int mt = 0; mt < 2; mt++)
        #pragma unroll
        for (int nt = 0; nt < 8; nt++)
            #pragma unroll
            for (int q = 0; q < 4; q++) acc[mt][nt][q] = 0.0f;

    const int NC = K / 32;
    float4 pa[4], pb[4];

    // prologue: load chunk 0
    #pragma unroll
    for (int i = 0; i < 4; i++) {
        pa[i] = *(const float4*)(Ag + (size_t)(gr + 32 * i) * K + gc);
        pb[i] = *(const float4*)(Wg + (size_t)(gr + 32 * i) * K + gc);
    }
    #pragma unroll
    for (int i = 0; i < 4; i++) {
        float* da = sA[0] + (gr + 32 * i) * GPITCH + gc;
        float* db = sB[0] + (gr + 32 * i) * GPITCH + gc;
        da[0] = to_tf32(pa[i].x); da[1] = to_tf32(pa[i].y);
        da[2] = to_tf32(pa[i].z); da[3] = to_tf32(pa[i].w);
        db[0] = to_tf32(pb[i].x); db[1] = to_tf32(pb[i].y);
        db[2] = to_tf32(pb[i].z); db[3] = to_tf32(pb[i].w);
    }
    __syncthreads();

    for (int c = 0; c < NC; c++) {
        const int buf = c & 1;
        if (c + 1 < NC) {
            const float* An = Ag + (c + 1) * 32;
            const float* Wn = Wg + (c + 1) * 32;
            #pragma unroll
            for (int i = 0; i < 4; i++) {
                pa[i] = *(const float4*)(An + (size_t)(gr + 32 * i) * K + gc);
                pb[i] = *(const float4*)(Wn + (size_t)(gr + 32 * i) * K + gc);
            }
        }

        // compute: 4 k-steps of 8
        #pragma unroll
        for (int ks = 0; ks < 4; ks++) {
            const int k0 = ks * 8;
            uint32_t af[2][4];
            #pragma unroll
            for (int mt = 0; mt < 2; mt++) {
                uint32_t addr = sbA[buf] +
                    (uint32_t)(((warpM * 32 + mt * 16 + a_row) * GPITCH + k0 + a_kq) * 4);
                ldmatrix_x4(af[mt][0], af[mt][1], af[mt][2], af[mt][3], addr);
            }
            uint32_t bf[8][2];
            #pragma unroll
            for (int nb = 0; nb < 4; nb++) {
                uint32_t addr = sbB[buf] +
                    (uint32_t)(((warpN * 64 + nb * 16 + b_row) * GPITCH + k0 + b_kq) * 4);
                uint32_t r0, r1, r2, r3;
                ldmatrix_x4(r0, r1, r2, r3, addr);
                bf[nb * 2 + 0][0] = r0; bf[nb * 2 + 0][1] = r1;
                bf[nb * 2 + 1][0] = r2; bf[nb * 2 + 1][1] = r3;
            }
            #pragma unroll
            for (int mt = 0; mt < 2; mt++)
                #pragma unroll
                for (int nt = 0; nt < 8; nt++)
                    mma_tf32(acc[mt][nt][0], acc[mt][nt][1],
                             acc[mt][nt][2], acc[mt][nt][3],
                             af[mt][0], af[mt][1], af[mt][2], af[mt][3],
                             bf[nt][0], bf[nt][1]);
        }

        if (c + 1 < NC) {
            __syncthreads();
            const int nb = buf ^ 1;
            #pragma unroll
            for (int i = 0; i < 4; i++) {
                float* da = sA[nb] + (gr + 32 * i) * GPITCH + gc;
                float* db = sB[nb] + (gr + 32 * i) * GPITCH + gc;
                da[0] = to_tf32(pa[i].x); da[1] = to_tf32(pa[i].y);
                da[2] = to_tf32(pa[i].z); da[3] = to_tf32(pa[i].w);
                db[0] = to_tf32(pb[i].x); db[1] = to_tf32(pb[i].y);
                db[2] = to_tf32(pb[i].z); db[3] = to_tf32(pb[i].w);
            }
            __syncthreads();
        }
    }

    // epilogue: bias + store.  acc layout: c0 (g, 2t), c1 (g, 2t+1),
    // c2 (g+8, 2t), c3 (g+8, 2t+1); g = lane>>2, t = lane&3.
    const int g = lane >> 2;
    const int t = lane & 3;
    float bb[8][2];
    #pragma unroll
    for (int nt = 0; nt < 8; nt++) {
        const int col = colN + warpN * 64 + nt * 8 + 2 * t;
        bb[nt][0] = __ldg(bias + col);
        bb[nt][1] = __ldg(bias + col + 1);
    }
    #pragma unroll
    for (int mt = 0; mt < 2; mt++) {
        const int r0_ = rowM + warpM * 32 + mt * 16 + g;
        #pragma unroll
        for (int nt = 0; nt < 8; nt++) {
            const int col = colN + warpN * 64 + nt * 8 + 2 * t;
            float2 v0, v1;
            v0.x = acc[mt][nt][0] + bb[nt][0];
            v0.y = acc[mt][nt][1] + bb[nt][1];
            v1.x = acc[mt][nt][2] + bb[nt][0];
            v1.y = acc[mt][nt][3] + bb[nt][1];
            *(float2*)(C + (size_t)r0_ * N + col)       = v0;
            *(float2*)(C + (size_t)(r0_ + 8) * N + col) = v1;
        }
    }
}

// ---------------------------------------------------------------------------
// Flash-attention fp32 (unchanged — passing, near fp32 roofline)
// ---------------------------------------------------------------------------
#define ATTN_PAD   68
#define ATTN_SMEM  (3 * 64 * ATTN_PAD * 4)

__global__ void __launch_bounds__(256)
attn_kernel(const float* __restrict__ Q, const float* __restrict__ Kg_,
            const float* __restrict__ Vg_, float* __restrict__ O)
{
    extern __shared__ float smf[];
    float* Qt = smf;
    float* KP = smf + 64 * ATTN_PAD;
    float* Vs = smf + 2 * 64 * ATTN_PAD;

    const int tid = threadIdx.x;
    const int tx  = tid & 15;
    const int ty  = tid >> 4;
    const int bh  = blockIdx.y;
    const int b   = bh / NH_;
    const int h   = bh % NH_;
    const int q0  = blockIdx.x * 64;

    const float* Qg = Q   + ((size_t)(b * S_ + q0)) * HID_ + h * HD_;
    const float* Kg = Kg_ + ((size_t)b * S_) * HID_ + h * HD_;
    const float* Vg = Vg_ + ((size_t)b * S_) * HID_ + h * HD_;

    {
        const int r  = tid >> 2;
        const int c0 = (tid & 3) * 16;
        const float4* src = (const float4*)(Qg + (size_t)r * HID_ + c0);
        #pragma unroll
        for (int i = 0; i < 4; i++) {
            float4 v = src[i];
            int d = c0 + 4 * i;
            Qt[(d + 0) * ATTN_PAD + r] = v.x;
            Qt[(d + 1) * ATTN_PAD + r] = v.y;
            Qt[(d + 2) * ATTN_PAD + r] = v.z;
            Qt[(d + 3) * ATTN_PAD + r] = v.w;
        }
    }

    float m[4], l[4], acc[4][4];
    #pragma unroll
    for (int i = 0; i < 4; i++) {
        m[i] = -1e30f; l[i] = 0.0f;
        #pragma unroll
        for (int j = 0; j < 4; j++) acc[i][j] = 0.0f;
    }

    const float SCALE = 0.125f;
    __syncthreads();

    for (int kt = 0; kt < S_; kt += 64) {
        {
            const int r  = tid >> 2;
            const int c0 = (tid & 3) * 16;
            const float4* ks = (const float4*)(Kg + (size_t)(kt + r) * HID_ + c0);
            #pragma unroll
            for (int i = 0; i < 4; i++) {
                float4 v = ks[i];
                int d = c0 + 4 * i;
                KP[(d + 0) * ATTN_PAD + r] = v.x;
                KP[(d + 1) * ATTN_PAD + r] = v.y;
                KP[(d + 2) * ATTN_PAD + r] = v.z;
                KP[(d + 3) * ATTN_PAD + r] = v.w;
            }
            const float4* vsrc = (const float4*)(Vg + (size_t)(kt + r) * HID_ + c0);
            float4* vdst = (float4*)(Vs + (size_t)r * ATTN_PAD + c0);
            #pragma unroll
            for (int i = 0; i < 4; i++) vdst[i] = vsrc[i];
        }
        __syncthreads();

        float s[4][4];
        #pragma unroll
        for (int i = 0; i < 4; i++)
            #pragma unroll
            for (int j = 0; j < 4; j++) s[i][j] = 0.0f;

        #pragma unroll 8
        for (int k = 0; k < HD_; k++) {
            float4 q4 = *(const float4*)(Qt + k * ATTN_PAD + 4 * ty);
            float4 k4 = *(const float4*)(KP + k * ATTN_PAD + 4 * tx);
            float qa[4] = {q4.x, q4.y, q4.z, q4.w};
            float kb[4] = {k4.x, k4.y, k4.z, k4.w};
            #pragma unroll
            for (int i = 0; i < 4; i++)
                #pragma unroll
                for (int j = 0; j < 4; j++)
                    s[i][j] = fmaf(qa[i], kb[j], s[i][j]);
        }

        float p[4][4];
        #pragma unroll
        for (int i = 0; i < 4; i++) {
            #pragma unroll
            for (int j = 0; j < 4; j++) s[i][j] *= SCALE;

            float mt = fmaxf(fmaxf(s[i][0], s[i][1]), fmaxf(s[i][2], s[i][3]));
            #pragma unroll
            for (int off = 8; off >= 1; off >>= 1)
                mt = fmaxf(mt, __shfl_xor_sync(0xffffffffu, mt, off, 16));

            float mnew = fmaxf(m[i], mt);
            float corr = __expf(m[i] - mnew);
            m[i] = mnew;
            l[i] *= corr;
            #pragma unroll
            for (int j = 0; j < 4; j++) acc[i][j] *= corr;

            float lt = 0.0f;
            #pragma unroll
            for (int j = 0; j < 4; j++) {
                p[i][j] = __expf(s[i][j] - mnew);
                lt += p[i][j];
            }
            #pragma unroll
            for (int off = 8; off >= 1; off >>= 1)
                lt += __shfl_xor_sync(0xffffffffu, lt, off, 16);
            l[i] += lt;
        }

        __syncthreads();

        #pragma unroll
        for (int j = 0; j < 4; j++)
            #pragma unroll
            for (int i = 0; i < 4; i++)
                KP[(4 * tx + j) * ATTN_PAD + 4 * ty + i] = p[i][j];
        __syncthreads();

        #pragma unroll 8
        for (int c = 0; c < 64; c++) {
            float4 p4 = *(const float4*)(KP + c * ATTN_PAD + 4 * ty);
            float4 v4 = *(const float4*)(Vs + c * ATTN_PAD + 4 * tx);
            float pa[4] = {p4.x, p4.y, p4.z, p4.w};
            float vb[4] = {v4.x, v4.y, v4.z, v4.w};
            #pragma unroll
            for (int i = 0; i < 4; i++)
                #pragma unroll
                for (int j = 0; j < 4; j++)
                    acc[i][j] = fmaf(pa[i], vb[j], acc[i][j]);
        }
        __syncthreads();
    }

    #pragma unroll
    for (int i = 0; i < 4; i++) {
        float inv = 1.0f / l[i];
        float4 o;
        o.x = acc[i][0] * inv; o.y = acc[i][1] * inv;
        o.z = acc[i][2] * inv; o.w = acc[i][3] * inv;
        *(float4*)(O + (size_t)(b * S_ + q0 + 4 * ty + i) * HID_ + h * HD_ + 4 * tx) = o;
    }
}

// ---------------------------------------------------------------------------
// Launch
// ---------------------------------------------------------------------------
extern "C" void kernel_launch(void* const* d_in, const int* in_sizes, int n_in,
                              void* d_out, int out_size)
{
    const float* x  = (const float*)d_in[0];
    const float* Wq = (const float*)d_in[1];
    const float* bq = (const float*)d_in[2];
    const float* Wk = (const float*)d_in[3];
    const float* bk = (const float*)d_in[4];
    const float* Wv = (const float*)d_in[5];
    const float* bv = (const float*)d_in[6];
    const float* Wo = (const float*)d_in[7];
    const float* bo = (const float*)d_in[8];
    float* out = (float*)d_out;

    float *qp, *kp, *vp, *ap;
    cudaGetSymbolAddress((void**)&qp, g_q);
    cudaGetSymbolAddress((void**)&kp, g_k);
    cudaGetSymbolAddress((void**)&vp, g_v);
    cudaGetSymbolAddress((void**)&ap, g_attn);

    cudaFuncSetAttribute(gemm_tc, cudaFuncAttributeMaxDynamicSharedMemorySize,
                         GEMM_SMEM);
    cudaFuncSetAttribute(attn_kernel,
                         cudaFuncAttributeMaxDynamicSharedMemorySize, ATTN_SMEM);

    // 1) fused QKV projections (tf32 mma.sync)
    {
        dim3 grid(HID_ / 128, MTOT / 128, 3);
        gemm_tc<<<grid, 256, GEMM_SMEM>>>(x, Wq, Wk, Wv, bq, bk, bv,
                                          qp, kp, vp, MTOT, HID_, HID_);
    }

    // 2) attention (fp32 SIMT flash attention)
    {
        dim3 grid(S_ / 64, B_ * NH_);
        attn_kernel<<<grid, 256, ATTN_SMEM>>>(qp, kp, vp, ap);
    }

    // 3) output projection (tf32 mma.sync)
    {
        dim3 grid(HID_ / 128, MTOT / 128, 1);
        gemm_tc<<<grid, 256, GEMM_SMEM>>>(ap, Wo, Wo, Wo, bo, bo, bo,
                                          out, out, out, MTOT, HID_, HID_);
    }
}

// round 4
// speedup vs baseline: 2.5144x; 1.8221x over previous
#include <cuda_runtime.h>
#include <cstdint>
#include <math.h>

#define B_   2
#define S_   2048
#define HID_ 1024
#define NH_  16
#define HD_  64
#define MTOT (B_ * S_)   // 4096

// ---------------------------------------------------------------------------
// Scratch buffers (no cudaMalloc allowed)
// ---------------------------------------------------------------------------
__device__ float g_q[MTOT * HID_];
__device__ float g_k[MTOT * HID_];
__device__ float g_v[MTOT * HID_];
__device__ float g_attn[MTOT * HID_];

// ---------------------------------------------------------------------------
// Helpers
// ---------------------------------------------------------------------------
__device__ __forceinline__ uint32_t smem_u32(const void* p) {
    uint32_t a;
    asm("{ .reg .u64 t; cvta.to.shared.u64 t, %1; cvt.u32.u64 %0, t; }"
        : "=r"(a) : "l"(p));
    return a;
}

__device__ __forceinline__ float to_tf32(float x) {
    uint32_t o;
    asm("cvt.rna.tf32.f32 %0, %1;" : "=r"(o) : "f"(x));
    return __uint_as_float(o);
}

__device__ __forceinline__ void ldmatrix_x4(uint32_t& r0, uint32_t& r1,
                                            uint32_t& r2, uint32_t& r3,
                                            uint32_t addr) {
    asm volatile("ldmatrix.sync.aligned.m8n8.x4.shared.b16 {%0,%1,%2,%3}, [%4];"
                 : "=r"(r0), "=r"(r1), "=r"(r2), "=r"(r3) : "r"(addr));
}

__device__ __forceinline__ void mma_tf32(float& c0, float& c1, float& c2, float& c3,
                                         uint32_t a0, uint32_t a1, uint32_t a2,
                                         uint32_t a3, uint32_t b0, uint32_t b1) {
    asm volatile(
        "mma.sync.aligned.m16n8k8.row.col.f32.tf32.tf32.f32 "
        "{%0,%1,%2,%3}, {%4,%5,%6,%7}, {%8,%9}, {%0,%1,%2,%3};"
        : "+f"(c0), "+f"(c1), "+f"(c2), "+f"(c3)
        : "r"(a0), "r"(a1), "r"(a2), "r"(a3), "r"(b0), "r"(b1));
}

__device__ __forceinline__ float quad_max(float v) {
    v = fmaxf(v, __shfl_xor_sync(0xffffffffu, v, 1));
    v = fmaxf(v, __shfl_xor_sync(0xffffffffu, v, 2));
    return v;
}
__device__ __forceinline__ float quad_sum(float v) {
    v += __shfl_xor_sync(0xffffffffu, v, 1);
    v += __shfl_xor_sync(0xffffffffu, v, 2);
    return v;
}

// ---------------------------------------------------------------------------
// tf32 mma.sync GEMM:  C[M,N] = A[M,K] @ W[N,K]^T + bias[N]   (as round 3)
// ---------------------------------------------------------------------------
#define GPITCH 36
#define GTILE_F (128 * GPITCH)
#define GEMM_SMEM (4 * GTILE_F * 4)

__global__ void __launch_bounds__(256)
gemm_tc(const float* __restrict__ A,
        const float* __restrict__ W0, const float* __restrict__ W1,
        const float* __restrict__ W2,
        const float* __restrict__ b0_, const float* __restrict__ b1_,
        const float* __restrict__ b2_,
        float* __restrict__ C0, float* __restrict__ C1, float* __restrict__ C2,
        int M, int N, int K)
{
    extern __shared__ float smf[];
    const int tid  = threadIdx.x;
    const int wid  = tid >> 5;
    const int lane = tid & 31;
    const int warpM = wid & 3;
    const int warpN = wid >> 2;

    const float* W; const float* bias; float* C;
    if (blockIdx.z == 0)      { W = W0; bias = b0_; C = C0; }
    else if (blockIdx.z == 1) { W = W1; bias = b1_; C = C1; }
    else                      { W = W2; bias = b2_; C = C2; }

    float* sA[2] = { smf,               smf + 2 * GTILE_F };
    float* sB[2] = { smf + GTILE_F,     smf + 3 * GTILE_F };

    const int rowM = blockIdx.y * 128;
    const int colN = blockIdx.x * 128;
    const float* Ag = A + (size_t)rowM * K;
    const float* Wg = W + (size_t)colN * K;

    const int gr = tid >> 3;
    const int gc = (tid & 7) * 4;

    const int a_row = ((lane >> 3) & 1) * 8 + (lane & 7);
    const int a_kq  = ((lane >> 4) & 1) * 4;
    const int b_row = ((lane >> 4) & 1) * 8 + (lane & 7);
    const int b_kq  = ((lane >> 3) & 1) * 4;

    const uint32_t sbA[2] = { smem_u32(sA[0]), smem_u32(sA[1]) };
    const uint32_t sbB[2] = { smem_u32(sB[0]), smem_u32(sB[1]) };

    float acc[2][8][4];
    #pragma unroll
    for (int mt = 0; mt < 2; mt++)
        #pragma unroll
        for (int nt = 0; nt < 8; nt++)
            #pragma unroll
            for (int q = 0; q < 4; q++) acc[mt][nt][q] = 0.0f;

    const int NC = K / 32;
    float4 pa[4], pb[4];

    #pragma unroll
    for (int i = 0; i < 4; i++) {
        pa[i] = *(const float4*)(Ag + (size_t)(gr + 32 * i) * K + gc);
        pb[i] = *(const float4*)(Wg + (size_t)(gr + 32 * i) * K + gc);
    }
    #pragma unroll
    for (int i = 0; i < 4; i++) {
        float* da = sA[0] + (gr + 32 * i) * GPITCH + gc;
        float* db = sB[0] + (gr + 32 * i) * GPITCH + gc;
        da[0] = to_tf32(pa[i].x); da[1] = to_tf32(pa[i].y);
        da[2] = to_tf32(pa[i].z); da[3] = to_tf32(pa[i].w);
        db[0] = to_tf32(pb[i].x); db[1] = to_tf32(pb[i].y);
        db[2] = to_tf32(pb[i].z); db[3] = to_tf32(pb[i].w);
    }
    __syncthreads();

    for (int c = 0; c < NC; c++) {
        const int buf = c & 1;
        if (c + 1 < NC) {
            const float* An = Ag + (c + 1) * 32;
            const float* Wn = Wg + (c + 1) * 32;
            #pragma unroll
            for (int i = 0; i < 4; i++) {
                pa[i] = *(const float4*)(An + (size_t)(gr + 32 * i) * K + gc);
                pb[i] = *(const float4*)(Wn + (size_t)(gr + 32 * i) * K + gc);
            }
        }

        #pragma unroll
        for (int ks = 0; ks < 4; ks++) {
            const int k0 = ks * 8;
            uint32_t af[2][4];
            #pragma unroll
            for (int mt = 0; mt < 2; mt++) {
                uint32_t addr = sbA[buf] +
                    (uint32_t)(((warpM * 32 + mt * 16 + a_row) * GPITCH + k0 + a_kq) * 4);
                ldmatrix_x4(af[mt][0], af[mt][1], af[mt][2], af[mt][3], addr);
            }
            uint32_t bf[8][2];
            #pragma unroll
            for (int nb = 0; nb < 4; nb++) {
                uint32_t addr = sbB[buf] +
                    (uint32_t)(((warpN * 64 + nb * 16 + b_row) * GPITCH + k0 + b_kq) * 4);
                uint32_t r0, r1, r2, r3;
                ldmatrix_x4(r0, r1, r2, r3, addr);
                bf[nb * 2 + 0][0] = r0; bf[nb * 2 + 0][1] = r1;
                bf[nb * 2 + 1][0] = r2; bf[nb * 2 + 1][1] = r3;
            }
            #pragma unroll
            for (int mt = 0; mt < 2; mt++)
                #pragma unroll
                for (int nt = 0; nt < 8; nt++)
                    mma_tf32(acc[mt][nt][0], acc[mt][nt][1],
                             acc[mt][nt][2], acc[mt][nt][3],
                             af[mt][0], af[mt][1], af[mt][2], af[mt][3],
                             bf[nt][0], bf[nt][1]);
        }

        if (c + 1 < NC) {
            __syncthreads();
            const int nb = buf ^ 1;
            #pragma unroll
            for (int i = 0; i < 4; i++) {
                float* da = sA[nb] + (gr + 32 * i) * GPITCH + gc;
                float* db = sB[nb] + (gr + 32 * i) * GPITCH + gc;
                da[0] = to_tf32(pa[i].x); da[1] = to_tf32(pa[i].y);
                da[2] = to_tf32(pa[i].z); da[3] = to_tf32(pa[i].w);
                db[0] = to_tf32(pb[i].x); db[1] = to_tf32(pb[i].y);
                db[2] = to_tf32(pb[i].z); db[3] = to_tf32(pb[i].w);
            }
            __syncthreads();
        }
    }

    const int g = lane >> 2;
    const int t = lane & 3;
    float bb[8][2];
    #pragma unroll
    for (int nt = 0; nt < 8; nt++) {
        const int col = colN + warpN * 64 + nt * 8 + 2 * t;
        bb[nt][0] = __ldg(bias + col);
        bb[nt][1] = __ldg(bias + col + 1);
    }
    #pragma unroll
    for (int mt = 0; mt < 2; mt++) {
        const int r0_ = rowM + warpM * 32 + mt * 16 + g;
        #pragma unroll
        for (int nt = 0; nt < 8; nt++) {
            const int col = colN + warpN * 64 + nt * 8 + 2 * t;
            float2 v0, v1;
            v0.x = acc[mt][nt][0] + bb[nt][0];
            v0.y = acc[mt][nt][1] + bb[nt][1];
            v1.x = acc[mt][nt][2] + bb[nt][0];
            v1.y = acc[mt][nt][3] + bb[nt][1];
            *(float2*)(C + (size_t)r0_ * N + col)       = v0;
            *(float2*)(C + (size_t)(r0_ + 8) * N + col) = v1;
        }
    }
}

// ---------------------------------------------------------------------------
// Tensor-core flash attention (tf32 mma.sync)
// CTA: 128 queries of one (b,h); 8 warps x 16 q-rows; key tiles of 64.
// smem: sQ[128][68] (tf32, pre-scaled), sK[64][68], sVt[64][68] (V^T),
//       sP: 8 x [16][68] per-warp P blocks.
// ---------------------------------------------------------------------------
#define BQ 128
#define BK 64
#define APITCH 68
#define SK_OFF   (128 * APITCH)
#define SVT_OFF  (SK_OFF + BK * APITCH)
#define SP_OFF   (SVT_OFF + HD_ * APITCH)
#define ATTN_SMEM ((SP_OFF + 128 * APITCH) * 4)    // 104448 B

__global__ void __launch_bounds__(256, 2)
attn_tc(const float* __restrict__ Q, const float* __restrict__ Kg_,
        const float* __restrict__ Vg_, float* __restrict__ O)
{
    extern __shared__ float smf[];
    float* sQ  = smf;
    float* sK  = smf + SK_OFF;
    float* sVt = smf + SVT_OFF;

    const int tid  = threadIdx.x;
    const int wid  = tid >> 5;
    const int lane = tid & 31;
    const int g    = lane >> 2;
    const int t    = lane & 3;
    const int bh   = blockIdx.y;
    const int b    = bh / NH_;
    const int h    = bh % NH_;
    const int q0   = blockIdx.x * BQ;

    float* myP = smf + SP_OFF + wid * 16 * APITCH;

    const uint32_t uQ  = smem_u32(sQ);
    const uint32_t uK  = smem_u32(sK);
    const uint32_t uVt = smem_u32(sVt);
    const uint32_t uP  = smem_u32(myP);

    const int a_row = ((lane >> 3) & 1) * 8 + (lane & 7);
    const int a_kq  = ((lane >> 4) & 1) * 4;
    const int b_row = ((lane >> 4) & 1) * 8 + (lane & 7);
    const int b_kq  = ((lane >> 3) & 1) * 4;

    // ---- stage Q (tf32, pre-scaled by 1/sqrt(HD)) ----
    {
        const int r  = tid >> 1;
        const int c0 = (tid & 1) * 32;
        const float* src = Q + (size_t)(b * S_ + q0 + r) * HID_ + h * HD_ + c0;
        float* dst = sQ + r * APITCH + c0;
        #pragma unroll
        for (int j = 0; j < 8; j++) {
            float4 v4 = *(const float4*)(src + 4 * j);
            dst[4 * j + 0] = to_tf32(v4.x * 0.125f);
            dst[4 * j + 1] = to_tf32(v4.y * 0.125f);
            dst[4 * j + 2] = to_tf32(v4.z * 0.125f);
            dst[4 * j + 3] = to_tf32(v4.w * 0.125f);
        }
    }

    float o[8][4];
    #pragma unroll
    for (int nt = 0; nt < 8; nt++)
        #pragma unroll
        for (int q = 0; q < 4; q++) o[nt][q] = 0.0f;
    float m0 = -1e30f, m1 = -1e30f, l0 = 0.0f, l1 = 0.0f;

    const float* Kg = Kg_ + (size_t)(b * S_) * HID_ + h * HD_;
    const float* Vg = Vg_ + (size_t)(b * S_) * HID_ + h * HD_;

    __syncthreads();

    for (int kt = 0; kt < S_; kt += BK) {
        // ---- load K tile (natural) + V tile (transposed) as tf32 ----
        {
            const int r  = tid >> 2;          // 0..63 key row
            const int c0 = (tid & 3) * 16;    // col base
            const float* ks = Kg + (size_t)(kt + r) * HID_ + c0;
            const float* vs = Vg + (size_t)(kt + r) * HID_ + c0;
            #pragma unroll
            for (int i = 0; i < 4; i++) {
                float4 kv = *(const float4*)(ks + 4 * i);
                float* d = sK + r * APITCH + c0 + 4 * i;
                d[0] = to_tf32(kv.x); d[1] = to_tf32(kv.y);
                d[2] = to_tf32(kv.z); d[3] = to_tf32(kv.w);
                float4 vv = *(const float4*)(vs + 4 * i);
                const int dc = c0 + 4 * i;
                sVt[(dc + 0) * APITCH + r] = to_tf32(vv.x);
                sVt[(dc + 1) * APITCH + r] = to_tf32(vv.y);
                sVt[(dc + 2) * APITCH + r] = to_tf32(vv.z);
                sVt[(dc + 3) * APITCH + r] = to_tf32(vv.w);
            }
        }
        __syncthreads();

        // ---- S = Q @ K^T ----
        float s[8][4];
        #pragma unroll
        for (int nt = 0; nt < 8; nt++)
            #pragma unroll
            for (int q = 0; q < 4; q++) s[nt][q] = 0.0f;

        #pragma unroll
        for (int kc = 0; kc < 8; kc++) {
            uint32_t qf[4];
            ldmatrix_x4(qf[0], qf[1], qf[2], qf[3],
                uQ + (uint32_t)(((wid * 16 + a_row) * APITCH + kc * 8 + a_kq) * 4));
            uint32_t bf[8][2];
            #pragma unroll
            for (int nb = 0; nb < 4; nb++) {
                uint32_t r0, r1, r2, r3;
                ldmatrix_x4(r0, r1, r2, r3,
                    uK + (uint32_t)(((nb * 16 + b_row) * APITCH + kc * 8 + b_kq) * 4));
                bf[nb * 2 + 0][0] = r0; bf[nb * 2 + 0][1] = r1;
                bf[nb * 2 + 1][0] = r2; bf[nb * 2 + 1][1] = r3;
            }
            #pragma unroll
            for (int nt = 0; nt < 8; nt++)
                mma_tf32(s[nt][0], s[nt][1], s[nt][2], s[nt][3],
                         qf[0], qf[1], qf[2], qf[3], bf[nt][0], bf[nt][1]);
        }

        // ---- online softmax (rows g and g+8 of this warp's 16) ----
        float mx0 = -1e30f, mx1 = -1e30f;
        #pragma unroll
        for (int nt = 0; nt < 8; nt++) {
            mx0 = fmaxf(mx0, fmaxf(s[nt][0], s[nt][1]));
            mx1 = fmaxf(mx1, fmaxf(s[nt][2], s[nt][3]));
        }
        mx0 = quad_max(mx0); mx1 = quad_max(mx1);
        const float mn0 = fmaxf(m0, mx0);
        const float mn1 = fmaxf(m1, mx1);
        const float c0r = __expf(m0 - mn0);
        const float c1r = __expf(m1 - mn1);
        m0 = mn0; m1 = mn1;

        float sum0 = 0.0f, sum1 = 0.0f;
        #pragma unroll
        for (int nt = 0; nt < 8; nt++) {
            float p0 = __expf(s[nt][0] - mn0);
            float p1 = __expf(s[nt][1] - mn0);
            float p2 = __expf(s[nt][2] - mn1);
            float p3 = __expf(s[nt][3] - mn1);
            sum0 += p0 + p1;
            sum1 += p2 + p3;
            o[nt][0] *= c0r; o[nt][1] *= c0r;
            o[nt][2] *= c1r; o[nt][3] *= c1r;
            float2 lo, hi;
            lo.x = to_tf32(p0); lo.y = to_tf32(p1);
            hi.x = to_tf32(p2); hi.y = to_tf32(p3);
            *(float2*)(myP + g * APITCH + nt * 8 + 2 * t)       = lo;
            *(float2*)(myP + (g + 8) * APITCH + nt * 8 + 2 * t) = hi;
        }
        sum0 = quad_sum(sum0); sum1 = quad_sum(sum1);
        l0 = l0 * c0r + sum0;
        l1 = l1 * c1r + sum1;
        __syncwarp();

        // ---- O += P @ V ----
        #pragma unroll
        for (int kc = 0; kc < 8; kc++) {
            uint32_t af[4];
            ldmatrix_x4(af[0], af[1], af[2], af[3],
                uP + (uint32_t)((a_row * APITCH + kc * 8 + a_kq) * 4));
            uint32_t vf[8][2];
            #pragma unroll
            for (int nb = 0; nb < 4; nb++) {
                uint32_t r0, r1, r2, r3;
                ldmatrix_x4(r0, r1, r2, r3,
                    uVt + (uint32_t)(((nb * 16 + b_row) * APITCH + kc * 8 + b_kq) * 4));
                vf[nb * 2 + 0][0] = r0; vf[nb * 2 + 0][1] = r1;
                vf[nb * 2 + 1][0] = r2; vf[nb * 2 + 1][1] = r3;
            }
            #pragma unroll
            for (int nt = 0; nt < 8; nt++)
                mma_tf32(o[nt][0], o[nt][1], o[nt][2], o[nt][3],
                         af[0], af[1], af[2], af[3], vf[nt][0], vf[nt][1]);
        }
        __syncthreads();   // before next tile overwrites sK/sVt
    }

    // ---- normalize + store ([B,S,HID] concat-heads) ----
    const float inv0 = 1.0f / l0;
    const float inv1 = 1.0f / l1;
    const size_t row0 = (size_t)(b * S_ + q0 + wid * 16 + g) * HID_ + h * HD_;
    #pragma unroll
    for (int nt = 0; nt < 8; nt++) {
        float2 v0, v1;
        v0.x = o[nt][0] * inv0; v0.y = o[nt][1] * inv0;
        v1.x = o[nt][2] * inv1; v1.y = o[nt][3] * inv1;
        *(float2*)(O + row0 + nt * 8 + 2 * t)              = v0;
        *(float2*)(O + row0 + 8 * HID_ + nt * 8 + 2 * t)   = v1;
    }
}

// ---------------------------------------------------------------------------
// Launch
// ---------------------------------------------------------------------------
extern "C" void kernel_launch(void* const* d_in, const int* in_sizes, int n_in,
                              void* d_out, int out_size)
{
    const float* x  = (const float*)d_in[0];
    const float* Wq = (const float*)d_in[1];
    const float* bq = (const float*)d_in[2];
    const float* Wk = (const float*)d_in[3];
    const float* bk = (const float*)d_in[4];
    const float* Wv = (const float*)d_in[5];
    const float* bv = (const float*)d_in[6];
    const float* Wo = (const float*)d_in[7];
    const float* bo = (const float*)d_in[8];
    float* out = (float*)d_out;

    float *qp, *kp, *vp, *ap;
    cudaGetSymbolAddress((void**)&qp, g_q);
    cudaGetSymbolAddress((void**)&kp, g_k);
    cudaGetSymbolAddress((void**)&vp, g_v);
    cudaGetSymbolAddress((void**)&ap, g_attn);

    cudaFuncSetAttribute(gemm_tc, cudaFuncAttributeMaxDynamicSharedMemorySize,
                         GEMM_SMEM);
    cudaFuncSetAttribute(attn_tc, cudaFuncAttributeMaxDynamicSharedMemorySize,
                         ATTN_SMEM);

    // 1) fused QKV projections (tf32 mma.sync)
    {
        dim3 grid(HID_ / 128, MTOT / 128, 3);
        gemm_tc<<<grid, 256, GEMM_SMEM>>>(x, Wq, Wk, Wv, bq, bk, bv,
                                          qp, kp, vp, MTOT, HID_, HID_);
    }

    // 2) attention (tf32 mma.sync flash attention)
    {
        dim3 grid(S_ / BQ, B_ * NH_);
        attn_tc<<<grid, 256, ATTN_SMEM>>>(qp, kp, vp, ap);
    }

    // 3) output projection (tf32 mma.sync)
    {
        dim3 grid(HID_ / 128, MTOT / 128, 1);
        gemm_tc<<<grid, 256, GEMM_SMEM>>>(ap, Wo, Wo, Wo, bo, bo, bo,
                                          out, out, out, MTOT, HID_, HID_);
    }
}

// round 5
// speedup vs baseline: 2.8378x; 1.1286x over previous
#include <cuda_runtime.h>
#include <cstdint>
#include <math.h>

#define B_   2
#define S_   2048
#define HID_ 1024
#define NH_  16
#define HD_  64
#define MTOT (B_ * S_)   // 4096

// ---------------------------------------------------------------------------
// Scratch buffers (no cudaMalloc allowed)
// ---------------------------------------------------------------------------
__device__ float g_q[MTOT * HID_];
__device__ float g_k[MTOT * HID_];
__device__ float g_v[MTOT * HID_];
__device__ float g_attn[MTOT * HID_];
__device__ float g_xt[MTOT * HID_];          // tf32-rounded x
__device__ float g_wt[3 * HID_ * HID_];      // tf32-rounded Wq,Wk,Wv
__device__ float g_wo[HID_ * HID_];          // tf32-rounded Wo

// ---------------------------------------------------------------------------
// Helpers
// ---------------------------------------------------------------------------
__device__ __forceinline__ uint32_t smem_u32(const void* p) {
    uint32_t a;
    asm("{ .reg .u64 t; cvta.to.shared.u64 t, %1; cvt.u32.u64 %0, t; }"
        : "=r"(a) : "l"(p));
    return a;
}

__device__ __forceinline__ float to_tf32(float x) {
    uint32_t o;
    asm("cvt.rna.tf32.f32 %0, %1;" : "=r"(o) : "f"(x));
    return __uint_as_float(o);
}

__device__ __forceinline__ void ldmatrix_x4(uint32_t& r0, uint32_t& r1,
                                            uint32_t& r2, uint32_t& r3,
                                            uint32_t addr) {
    asm volatile("ldmatrix.sync.aligned.m8n8.x4.shared.b16 {%0,%1,%2,%3}, [%4];"
                 : "=r"(r0), "=r"(r1), "=r"(r2), "=r"(r3) : "r"(addr));
}

__device__ __forceinline__ void mma_tf32(float& c0, float& c1, float& c2, float& c3,
                                         uint32_t a0, uint32_t a1, uint32_t a2,
                                         uint32_t a3, uint32_t b0, uint32_t b1) {
    asm volatile(
        "mma.sync.aligned.m16n8k8.row.col.f32.tf32.tf32.f32 "
        "{%0,%1,%2,%3}, {%4,%5,%6,%7}, {%8,%9}, {%0,%1,%2,%3};"
        : "+f"(c0), "+f"(c1), "+f"(c2), "+f"(c3)
        : "r"(a0), "r"(a1), "r"(a2), "r"(a3), "r"(b0), "r"(b1));
}

__device__ __forceinline__ float quad_max(float v) {
    v = fmaxf(v, __shfl_xor_sync(0xffffffffu, v, 1));
    v = fmaxf(v, __shfl_xor_sync(0xffffffffu, v, 2));
    return v;
}
__device__ __forceinline__ float quad_sum(float v) {
    v += __shfl_xor_sync(0xffffffffu, v, 1);
    v += __shfl_xor_sync(0xffffffffu, v, 2);
    return v;
}

#define CPA16(dst, src) \
    asm volatile("cp.async.cg.shared.global [%0], [%1], 16;" \
                 :: "r"(dst), "l"(src) : "memory")
#define CPA_COMMIT() asm volatile("cp.async.commit_group;" ::: "memory")
#define CPA_WAIT1()  asm volatile("cp.async.wait_group 1;" ::: "memory")

// ---------------------------------------------------------------------------
// tf32 pre-rounding pass (float4 vectorized)
// ---------------------------------------------------------------------------
__global__ void __launch_bounds__(256)
round_vec(const float* __restrict__ in, float* __restrict__ out, int n4)
{
    int i = blockIdx.x * 256 + threadIdx.x;
    if (i < n4) {
        float4 v = ((const float4*)in)[i];
        float4 o;
        o.x = to_tf32(v.x); o.y = to_tf32(v.y);
        o.z = to_tf32(v.z); o.w = to_tf32(v.w);
        ((float4*)out)[i] = o;
    }
}

// ---------------------------------------------------------------------------
// tf32 mma.sync GEMM, cp.async 3-stage pipeline:
//   C[M,N] = A[M,K] @ W[N,K]^T + bias[N]
// A and W must be PRE-ROUNDED to tf32. 128x128x32 CTA tile, 256 threads,
// 8 warps (4x2), 32x64 warp tile. Swizzled smem (16B unit ^= row&7).
// round_out != 0 -> epilogue stores tf32-rounded values.
// ---------------------------------------------------------------------------
#define STAGE_BYTES 32768                 // A 16KB + B 16KB
#define GEMM_SMEM (3 * STAGE_BYTES)       // 98304

__global__ void __launch_bounds__(256)
gemm_tc(const float* __restrict__ A,
        const float* __restrict__ W0, const float* __restrict__ W1,
        const float* __restrict__ W2,
        const float* __restrict__ b0_, const float* __restrict__ b1_,
        const float* __restrict__ b2_,
        float* __restrict__ C0, float* __restrict__ C1, float* __restrict__ C2,
        int M, int N, int K, int round_out)
{
    extern __shared__ char smc[];
    const uint32_t sbase = smem_u32(smc);
    const int tid  = threadIdx.x;
    const int wid  = tid >> 5;
    const int lane = tid & 31;
    const int warpM = wid & 3;
    const int warpN = wid >> 2;

    const float* W; const float* bias; float* C;
    if (blockIdx.z == 0)      { W = W0; bias = b0_; C = C0; }
    else if (blockIdx.z == 1) { W = W1; bias = b1_; C = C1; }
    else                      { W = W2; bias = b2_; C = C2; }

    const int rowM = blockIdx.y * 128;
    const int colN = blockIdx.x * 128;
    const float* Ag = A + (size_t)rowM * K;
    const float* Wg = W + (size_t)colN * K;

    // cp.async mapping: thread -> (row, 4 consecutive 16B units)
    const int cr = tid >> 1;            // 0..127
    const int cu = (tid & 1) * 4;       // 0 or 4
    const float* agr = Ag + (size_t)cr * K;
    const float* wgr = Wg + (size_t)cr * K;

    // ldmatrix per-lane offsets
    const int a_row = ((lane >> 3) & 1) * 8 + (lane & 7);
    const int a_u   = (lane >> 4) & 1;      // k-quad unit (0 or 1)
    const int b_row = ((lane >> 4) & 1) * 8 + (lane & 7);
    const int b_u   = (lane >> 3) & 1;

    float acc[2][8][4];
    #pragma unroll
    for (int mt = 0; mt < 2; mt++)
        #pragma unroll
        for (int nt = 0; nt < 8; nt++)
            #pragma unroll
            for (int q = 0; q < 4; q++) acc[mt][nt][q] = 0.0f;

    const int NC = K / 32;

    // prologue: stages for chunks 0 and 1
    #pragma unroll
    for (int s = 0; s < 2; s++) {
        const uint32_t sa = sbase + s * STAGE_BYTES + cr * 128;
        const float* ac = agr + s * 32;
        const float* wc = wgr + s * 32;
        #pragma unroll
        for (int i = 0; i < 4; i++) {
            const int u = cu + i;
            const uint32_t off = (uint32_t)((u ^ (cr & 7)) << 4);
            CPA16(sa + off,         ac + u * 4);
            CPA16(sa + 16384 + off, wc + u * 4);
        }
        CPA_COMMIT();
    }

    for (int c = 0; c < NC; c++) {
        const int buf = c % 3;
        CPA_WAIT1();
        __syncthreads();

        // issue chunk c+2 into buffer (c+2)%3
        if (c + 2 < NC) {
            const int s = (c + 2) % 3;
            const uint32_t sa = sbase + s * STAGE_BYTES + cr * 128;
            const float* ac = agr + (c + 2) * 32;
            const float* wc = wgr + (c + 2) * 32;
            #pragma unroll
            for (int i = 0; i < 4; i++) {
                const int u = cu + i;
                const uint32_t off = (uint32_t)((u ^ (cr & 7)) << 4);
                CPA16(sa + off,         ac + u * 4);
                CPA16(sa + 16384 + off, wc + u * 4);
            }
        }
        CPA_COMMIT();

        // compute chunk c
        const uint32_t stA = sbase + buf * STAGE_BYTES;
        const uint32_t stB = stA + 16384;
        #pragma unroll
        for (int kc = 0; kc < 4; kc++) {
            uint32_t af[2][4];
            #pragma unroll
            for (int mt = 0; mt < 2; mt++) {
                const int row = warpM * 32 + mt * 16 + a_row;
                const uint32_t addr = stA + (uint32_t)(row * 128) +
                    (uint32_t)((((kc * 2 + a_u) ^ (row & 7))) << 4);
                ldmatrix_x4(af[mt][0], af[mt][1], af[mt][2], af[mt][3], addr);
            }
            uint32_t bf[8][2];
            #pragma unroll
            for (int nb = 0; nb < 4; nb++) {
                const int row = warpN * 64 + nb * 16 + b_row;
                const uint32_t addr = stB + (uint32_t)(row * 128) +
                    (uint32_t)((((kc * 2 + b_u) ^ (row & 7))) << 4);
                uint32_t r0, r1, r2, r3;
                ldmatrix_x4(r0, r1, r2, r3, addr);
                bf[nb * 2 + 0][0] = r0; bf[nb * 2 + 0][1] = r1;
                bf[nb * 2 + 1][0] = r2; bf[nb * 2 + 1][1] = r3;
            }
            #pragma unroll
            for (int mt = 0; mt < 2; mt++)
                #pragma unroll
                for (int nt = 0; nt < 8; nt++)
                    mma_tf32(acc[mt][nt][0], acc[mt][nt][1],
                             acc[mt][nt][2], acc[mt][nt][3],
                             af[mt][0], af[mt][1], af[mt][2], af[mt][3],
                             bf[nt][0], bf[nt][1]);
        }
    }

    // epilogue: bias + (optional tf32 rounding) + store
    const int g = lane >> 2;
    const int t = lane & 3;
    float bb[8][2];
    #pragma unroll
    for (int nt = 0; nt < 8; nt++) {
        const int col = colN + warpN * 64 + nt * 8 + 2 * t;
        bb[nt][0] = __ldg(bias + col);
        bb[nt][1] = __ldg(bias + col + 1);
    }
    #pragma unroll
    for (int mt = 0; mt < 2; mt++) {
        const int r0_ = rowM + warpM * 32 + mt * 16 + g;
        #pragma unroll
        for (int nt = 0; nt < 8; nt++) {
            const int col = colN + warpN * 64 + nt * 8 + 2 * t;
            float2 v0, v1;
            v0.x = acc[mt][nt][0] + bb[nt][0];
            v0.y = acc[mt][nt][1] + bb[nt][1];
            v1.x = acc[mt][nt][2] + bb[nt][0];
            v1.y = acc[mt][nt][3] + bb[nt][1];
            if (round_out) {
                v0.x = to_tf32(v0.x); v0.y = to_tf32(v0.y);
                v1.x = to_tf32(v1.x); v1.y = to_tf32(v1.y);
            }
            *(float2*)(C + (size_t)r0_ * N + col)       = v0;
            *(float2*)(C + (size_t)(r0_ + 8) * N + col) = v1;
        }
    }
}

// ---------------------------------------------------------------------------
// Tensor-core flash attention (tf32 mma.sync). Inputs q/k/v pre-rounded tf32;
// output written tf32-rounded (consumed by o-proj GEMM via cp.async).
// ---------------------------------------------------------------------------
#define BQ 128
#define BK 64
#define APITCH 68
#define SK_OFF   (128 * APITCH)
#define SVT_OFF  (SK_OFF + BK * APITCH)
#define SP_OFF   (SVT_OFF + HD_ * APITCH)
#define ATTN_SMEM ((SP_OFF + 128 * APITCH) * 4)    // 104448 B

__global__ void __launch_bounds__(256, 2)
attn_tc(const float* __restrict__ Q, const float* __restrict__ Kg_,
        const float* __restrict__ Vg_, float* __restrict__ O)
{
    extern __shared__ float smf[];
    float* sQ  = smf;
    float* sK  = smf + SK_OFF;
    float* sVt = smf + SVT_OFF;

    const int tid  = threadIdx.x;
    const int wid  = tid >> 5;
    const int lane = tid & 31;
    const int g    = lane >> 2;
    const int t    = lane & 3;
    const int bh   = blockIdx.y;
    const int b    = bh / NH_;
    const int h    = bh % NH_;
    const int q0   = blockIdx.x * BQ;

    float* myP = smf + SP_OFF + wid * 16 * APITCH;

    const uint32_t uQ  = smem_u32(sQ);
    const uint32_t uK  = smem_u32(sK);
    const uint32_t uVt = smem_u32(sVt);
    const uint32_t uP  = smem_u32(myP);

    const int a_row = ((lane >> 3) & 1) * 8 + (lane & 7);
    const int a_kq  = ((lane >> 4) & 1) * 4;
    const int b_row = ((lane >> 4) & 1) * 8 + (lane & 7);
    const int b_kq  = ((lane >> 3) & 1) * 4;

    // ---- stage Q (pre-rounded; x0.125 is exact, stays tf32) ----
    {
        const int r  = tid >> 1;
        const int c0 = (tid & 1) * 32;
        const float* src = Q + (size_t)(b * S_ + q0 + r) * HID_ + h * HD_ + c0;
        float* dst = sQ + r * APITCH + c0;
        #pragma unroll
        for (int j = 0; j < 8; j++) {
            float4 v4 = *(const float4*)(src + 4 * j);
            dst[4 * j + 0] = v4.x * 0.125f;
            dst[4 * j + 1] = v4.y * 0.125f;
            dst[4 * j + 2] = v4.z * 0.125f;
            dst[4 * j + 3] = v4.w * 0.125f;
        }
    }

    float o[8][4];
    #pragma unroll
    for (int nt = 0; nt < 8; nt++)
        #pragma unroll
        for (int q = 0; q < 4; q++) o[nt][q] = 0.0f;
    float m0 = -1e30f, m1 = -1e30f, l0 = 0.0f, l1 = 0.0f;

    const float* Kg = Kg_ + (size_t)(b * S_) * HID_ + h * HD_;
    const float* Vg = Vg_ + (size_t)(b * S_) * HID_ + h * HD_;

    __syncthreads();

    for (int kt = 0; kt < S_; kt += BK) {
        // ---- load K tile (natural) + V tile (transposed); already tf32 ----
        {
            const int r  = tid >> 2;
            const int c0 = (tid & 3) * 16;
            const float* ks = Kg + (size_t)(kt + r) * HID_ + c0;
            const float* vs = Vg + (size_t)(kt + r) * HID_ + c0;
            #pragma unroll
            for (int i = 0; i < 4; i++) {
                float4 kv = *(const float4*)(ks + 4 * i);
                *(float4*)(sK + r * APITCH + c0 + 4 * i) = kv;
                float4 vv = *(const float4*)(vs + 4 * i);
                const int dc = c0 + 4 * i;
                sVt[(dc + 0) * APITCH + r] = vv.x;
                sVt[(dc + 1) * APITCH + r] = vv.y;
                sVt[(dc + 2) * APITCH + r] = vv.z;
                sVt[(dc + 3) * APITCH + r] = vv.w;
            }
        }
        __syncthreads();

        // ---- S = Q @ K^T ----
        float s[8][4];
        #pragma unroll
        for (int nt = 0; nt < 8; nt++)
            #pragma unroll
            for (int q = 0; q < 4; q++) s[nt][q] = 0.0f;

        #pragma unroll
        for (int kc = 0; kc < 8; kc++) {
            uint32_t qf[4];
            ldmatrix_x4(qf[0], qf[1], qf[2], qf[3],
                uQ + (uint32_t)(((wid * 16 + a_row) * APITCH + kc * 8 + a_kq) * 4));
            uint32_t bf[8][2];
            #pragma unroll
            for (int nb = 0; nb < 4; nb++) {
                uint32_t r0, r1, r2, r3;
                ldmatrix_x4(r0, r1, r2, r3,
                    uK + (uint32_t)(((nb * 16 + b_row) * APITCH + kc * 8 + b_kq) * 4));
                bf[nb * 2 + 0][0] = r0; bf[nb * 2 + 0][1] = r1;
                bf[nb * 2 + 1][0] = r2; bf[nb * 2 + 1][1] = r3;
            }
            #pragma unroll
            for (int nt = 0; nt < 8; nt++)
                mma_tf32(s[nt][0], s[nt][1], s[nt][2], s[nt][3],
                         qf[0], qf[1], qf[2], qf[3], bf[nt][0], bf[nt][1]);
        }

        // ---- online softmax ----
        float mx0 = -1e30f, mx1 = -1e30f;
        #pragma unroll
        for (int nt = 0; nt < 8; nt++) {
            mx0 = fmaxf(mx0, fmaxf(s[nt][0], s[nt][1]));
            mx1 = fmaxf(mx1, fmaxf(s[nt][2], s[nt][3]));
        }
        mx0 = quad_max(mx0); mx1 = quad_max(mx1);
        const float mn0 = fmaxf(m0, mx0);
        const float mn1 = fmaxf(m1, mx1);
        const float c0r = __expf(m0 - mn0);
        const float c1r = __expf(m1 - mn1);
        m0 = mn0; m1 = mn1;

        float sum0 = 0.0f, sum1 = 0.0f;
        #pragma unroll
        for (int nt = 0; nt < 8; nt++) {
            float p0 = __expf(s[nt][0] - mn0);
            float p1 = __expf(s[nt][1] - mn0);
            float p2 = __expf(s[nt][2] - mn1);
            float p3 = __expf(s[nt][3] - mn1);
            sum0 += p0 + p1;
            sum1 += p2 + p3;
            o[nt][0] *= c0r; o[nt][1] *= c0r;
            o[nt][2] *= c1r; o[nt][3] *= c1r;
            float2 lo, hi;
            lo.x = to_tf32(p0); lo.y = to_tf32(p1);
            hi.x = to_tf32(p2); hi.y = to_tf32(p3);
            *(float2*)(myP + g * APITCH + nt * 8 + 2 * t)       = lo;
            *(float2*)(myP + (g + 8) * APITCH + nt * 8 + 2 * t) = hi;
        }
        sum0 = quad_sum(sum0); sum1 = quad_sum(sum1);
        l0 = l0 * c0r + sum0;
        l1 = l1 * c1r + sum1;
        __syncwarp();

        // ---- O += P @ V ----
        #pragma unroll
        for (int kc = 0; kc < 8; kc++) {
            uint32_t af[4];
            ldmatrix_x4(af[0], af[1], af[2], af[3],
                uP + (uint32_t)((a_row * APITCH + kc * 8 + a_kq) * 4));
            uint32_t vf[8][2];
            #pragma unroll
            for (int nb = 0; nb < 4; nb++) {
                uint32_t r0, r1, r2, r3;
                ldmatrix_x4(r0, r1, r2, r3,
                    uVt + (uint32_t)(((nb * 16 + b_row) * APITCH + kc * 8 + b_kq) * 4));
                vf[nb * 2 + 0][0] = r0; vf[nb * 2 + 0][1] = r1;
                vf[nb * 2 + 1][0] = r2; vf[nb * 2 + 1][1] = r3;
            }
            #pragma unroll
            for (int nt = 0; nt < 8; nt++)
                mma_tf32(o[nt][0], o[nt][1], o[nt][2], o[nt][3],
                         af[0], af[1], af[2], af[3], vf[nt][0], vf[nt][1]);
        }
        __syncthreads();
    }

    // ---- normalize + store tf32-rounded ([B,S,HID] concat-heads) ----
    const float inv0 = 1.0f / l0;
    const float inv1 = 1.0f / l1;
    const size_t row0 = (size_t)(b * S_ + q0 + wid * 16 + g) * HID_ + h * HD_;
    #pragma unroll
    for (int nt = 0; nt < 8; nt++) {
        float2 v0, v1;
        v0.x = to_tf32(o[nt][0] * inv0); v0.y = to_tf32(o[nt][1] * inv0);
        v1.x = to_tf32(o[nt][2] * inv1); v1.y = to_tf32(o[nt][3] * inv1);
        *(float2*)(O + row0 + nt * 8 + 2 * t)              = v0;
        *(float2*)(O + row0 + 8 * HID_ + nt * 8 + 2 * t)   = v1;
    }
}

// ---------------------------------------------------------------------------
// Launch
// ---------------------------------------------------------------------------
extern "C" void kernel_launch(void* const* d_in, const int* in_sizes, int n_in,
                              void* d_out, int out_size)
{
    const float* x  = (const float*)d_in[0];
    const float* Wq = (const float*)d_in[1];
    const float* bq = (const float*)d_in[2];
    const float* Wk = (const float*)d_in[3];
    const float* bk = (const float*)d_in[4];
    const float* Wv = (const float*)d_in[5];
    const float* bv = (const float*)d_in[6];
    const float* Wo = (const float*)d_in[7];
    const float* bo = (const float*)d_in[8];
    float* out = (float*)d_out;

    float *qp, *kp, *vp, *ap, *xt, *wt, *wo;
    cudaGetSymbolAddress((void**)&qp, g_q);
    cudaGetSymbolAddress((void**)&kp, g_k);
    cudaGetSymbolAddress((void**)&vp, g_v);
    cudaGetSymbolAddress((void**)&ap, g_attn);
    cudaGetSymbolAddress((void**)&xt, g_xt);
    cudaGetSymbolAddress((void**)&wt, g_wt);
    cudaGetSymbolAddress((void**)&wo, g_wo);

    cudaFuncSetAttribute(gemm_tc, cudaFuncAttributeMaxDynamicSharedMemorySize,
                         GEMM_SMEM);
    cudaFuncSetAttribute(attn_tc, cudaFuncAttributeMaxDynamicSharedMemorySize,
                         ATTN_SMEM);

    // 0) pre-round inputs/weights to tf32 (RNA)
    {
        const int NX4 = MTOT * HID_ / 4;          // 1M float4
        const int NW4 = HID_ * HID_ / 4;          // 256K float4
        round_vec<<<NX4 / 256, 256>>>(x,  xt, NX4);
        round_vec<<<NW4 / 256, 256>>>(Wq, wt,                NW4);
        round_vec<<<NW4 / 256, 256>>>(Wk, wt + HID_ * HID_,  NW4);
        round_vec<<<NW4 / 256, 256>>>(Wv, wt + 2 * HID_ * HID_, NW4);
        round_vec<<<NW4 / 256, 256>>>(Wo, wo, NW4);
    }

    // 1) fused QKV projections (cp.async tf32 GEMM, rounded outputs)
    {
        dim3 grid(HID_ / 128, MTOT / 128, 3);
        gemm_tc<<<grid, 256, GEMM_SMEM>>>(xt, wt, wt + HID_ * HID_,
                                          wt + 2 * HID_ * HID_,
                                          bq, bk, bv, qp, kp, vp,
                                          MTOT, HID_, HID_, 1);
    }

    // 2) attention (tf32 mma.sync flash attention, rounded output)
    {
        dim3 grid(S_ / BQ, B_ * NH_);
        attn_tc<<<grid, 256, ATTN_SMEM>>>(qp, kp, vp, ap);
    }

    // 3) output projection (raw fp32 output)
    {
        dim3 grid(HID_ / 128, MTOT / 128, 1);
        gemm_tc<<<grid, 256, GEMM_SMEM>>>(ap, wo, wo, wo, bo, bo, bo,
                                          out, out, out, MTOT, HID_, HID_, 0);
    }
}

// round 6
// speedup vs baseline: 3.1941x; 1.1256x over previous
#include <cuda_runtime.h>
#include <cstdint>
#include <math.h>

#define B_   2
#define S_   2048
#define HID_ 1024
#define NH_  16
#define HD_  64
#define MTOT (B_ * S_)   // 4096

// ---------------------------------------------------------------------------
// Scratch buffers (no cudaMalloc allowed)
// g_v holds V TRANSPOSED per (b,h): layout [(b*16+h)*64 + d][s], pitch S_.
// ---------------------------------------------------------------------------
__device__ float g_q[MTOT * HID_];
__device__ float g_v[MTOT * HID_];
__device__ float g_k[MTOT * HID_];
__device__ float g_attn[MTOT * HID_];
__device__ float g_xt[MTOT * HID_];          // tf32-rounded x
__device__ float g_wt[3 * HID_ * HID_];      // tf32-rounded Wq,Wk,Wv
__device__ float g_wo[HID_ * HID_];          // tf32-rounded Wo

// ---------------------------------------------------------------------------
// Helpers
// ---------------------------------------------------------------------------
__device__ __forceinline__ uint32_t smem_u32(const void* p) {
    uint32_t a;
    asm("{ .reg .u64 t; cvta.to.shared.u64 t, %1; cvt.u32.u64 %0, t; }"
        : "=r"(a) : "l"(p));
    return a;
}

__device__ __forceinline__ float to_tf32(float x) {
    uint32_t o;
    asm("cvt.rna.tf32.f32 %0, %1;" : "=r"(o) : "f"(x));
    return __uint_as_float(o);
}

__device__ __forceinline__ void ldmatrix_x4(uint32_t& r0, uint32_t& r1,
                                            uint32_t& r2, uint32_t& r3,
                                            uint32_t addr) {
    asm volatile("ldmatrix.sync.aligned.m8n8.x4.shared.b16 {%0,%1,%2,%3}, [%4];"
                 : "=r"(r0), "=r"(r1), "=r"(r2), "=r"(r3) : "r"(addr));
}

__device__ __forceinline__ void mma_tf32(float& c0, float& c1, float& c2, float& c3,
                                         uint32_t a0, uint32_t a1, uint32_t a2,
                                         uint32_t a3, uint32_t b0, uint32_t b1) {
    asm volatile(
        "mma.sync.aligned.m16n8k8.row.col.f32.tf32.tf32.f32 "
        "{%0,%1,%2,%3}, {%4,%5,%6,%7}, {%8,%9}, {%0,%1,%2,%3};"
        : "+f"(c0), "+f"(c1), "+f"(c2), "+f"(c3)
        : "r"(a0), "r"(a1), "r"(a2), "r"(a3), "r"(b0), "r"(b1));
}

__device__ __forceinline__ float quad_max(float v) {
    v = fmaxf(v, __shfl_xor_sync(0xffffffffu, v, 1));
    v = fmaxf(v, __shfl_xor_sync(0xffffffffu, v, 2));
    return v;
}
__device__ __forceinline__ float quad_sum(float v) {
    v += __shfl_xor_sync(0xffffffffu, v, 1);
    v += __shfl_xor_sync(0xffffffffu, v, 2);
    return v;
}

#define CPA16(dst, src) \
    asm volatile("cp.async.cg.shared.global [%0], [%1], 16;" \
                 :: "r"(dst), "l"(src) : "memory")
#define CPA_COMMIT() asm volatile("cp.async.commit_group;" ::: "memory")
#define CPA_WAIT1()  asm volatile("cp.async.wait_group 1;" ::: "memory")
#define CPA_WAIT0()  asm volatile("cp.async.wait_group 0;" ::: "memory")

// ---------------------------------------------------------------------------
// tf32 pre-rounding pass
// ---------------------------------------------------------------------------
__global__ void __launch_bounds__(256)
round_vec(const float* __restrict__ in, float* __restrict__ out, int n4)
{
    int i = blockIdx.x * 256 + threadIdx.x;
    if (i < n4) {
        float4 v = ((const float4*)in)[i];
        float4 o;
        o.x = to_tf32(v.x); o.y = to_tf32(v.y);
        o.z = to_tf32(v.z); o.w = to_tf32(v.w);
        ((float4*)out)[i] = o;
    }
}

// ---------------------------------------------------------------------------
// tf32 mma.sync GEMM, cp.async 3-stage pipeline, 512 threads (16 warps 4x4),
// CTA tile 128x128x32, warp tile 32x32.
//   C[M,N] = A[M,K] @ W[N,K]^T + bias[N]      (A, W pre-rounded to tf32)
// mode: 0 = raw store, 1 = tf32-rounded store, 2 = tf32-rounded store
//       TRANSPOSED per (b,h) head block (for V): dst[(b*1024+n)*2048 + s].
// ---------------------------------------------------------------------------
#define STAGE_BYTES 32768                 // A 16KB + B 16KB
#define GEMM_SMEM (3 * STAGE_BYTES)       // 98304

__global__ void __launch_bounds__(512)
gemm_tc(const float* __restrict__ A,
        const float* __restrict__ W0, const float* __restrict__ W1,
        const float* __restrict__ W2,
        const float* __restrict__ b0_, const float* __restrict__ b1_,
        const float* __restrict__ b2_,
        float* __restrict__ C0, float* __restrict__ C1, float* __restrict__ C2,
        int M, int N, int K, int mode0, int mode1, int mode2)
{
    extern __shared__ char smc[];
    const uint32_t sbase = smem_u32(smc);
    const int tid  = threadIdx.x;
    const int wid  = tid >> 5;
    const int lane = tid & 31;
    const int warpM = wid & 3;          // 4 warp-rows
    const int warpN = wid >> 2;         // 4 warp-cols

    const float* W; const float* bias; float* C; int mode;
    if (blockIdx.z == 0)      { W = W0; bias = b0_; C = C0; mode = mode0; }
    else if (blockIdx.z == 1) { W = W1; bias = b1_; C = C1; mode = mode1; }
    else                      { W = W2; bias = b2_; C = C2; mode = mode2; }

    const int rowM = blockIdx.y * 128;
    const int colN = blockIdx.x * 128;
    const float* Ag = A + (size_t)rowM * K;
    const float* Wg = W + (size_t)colN * K;

    // cp.async mapping: 512 threads; thread -> (row, 2 consecutive 16B units)
    const int cr = tid >> 2;            // 0..127
    const int cu = (tid & 3) * 2;       // 0,2,4,6
    const float* agr = Ag + (size_t)cr * K;
    const float* wgr = Wg + (size_t)cr * K;

    // ldmatrix per-lane offsets
    const int a_row = ((lane >> 3) & 1) * 8 + (lane & 7);
    const int a_u   = (lane >> 4) & 1;
    const int b_row = ((lane >> 4) & 1) * 8 + (lane & 7);
    const int b_u   = (lane >> 3) & 1;

    float acc[2][4][4];
    #pragma unroll
    for (int mt = 0; mt < 2; mt++)
        #pragma unroll
        for (int nt = 0; nt < 4; nt++)
            #pragma unroll
            for (int q = 0; q < 4; q++) acc[mt][nt][q] = 0.0f;

    const int NC = K / 32;

    #pragma unroll
    for (int s = 0; s < 2; s++) {
        const uint32_t sa = sbase + s * STAGE_BYTES + cr * 128;
        const float* ac = agr + s * 32;
        const float* wc = wgr + s * 32;
        #pragma unroll
        for (int i = 0; i < 2; i++) {
            const int u = cu + i;
            const uint32_t off = (uint32_t)((u ^ (cr & 7)) << 4);
            CPA16(sa + off,         ac + u * 4);
            CPA16(sa + 16384 + off, wc + u * 4);
        }
        CPA_COMMIT();
    }

    for (int c = 0; c < NC; c++) {
        const int buf = c % 3;
        CPA_WAIT1();
        __syncthreads();

        if (c + 2 < NC) {
            const int s = (c + 2) % 3;
            const uint32_t sa = sbase + s * STAGE_BYTES + cr * 128;
            const float* ac = agr + (c + 2) * 32;
            const float* wc = wgr + (c + 2) * 32;
            #pragma unroll
            for (int i = 0; i < 2; i++) {
                const int u = cu + i;
                const uint32_t off = (uint32_t)((u ^ (cr & 7)) << 4);
                CPA16(sa + off,         ac + u * 4);
                CPA16(sa + 16384 + off, wc + u * 4);
            }
        }
        CPA_COMMIT();

        const uint32_t stA = sbase + buf * STAGE_BYTES;
        const uint32_t stB = stA + 16384;
        #pragma unroll
        for (int kc = 0; kc < 4; kc++) {
            uint32_t af[2][4];
            #pragma unroll
            for (int mt = 0; mt < 2; mt++) {
                const int row = warpM * 32 + mt * 16 + a_row;
                const uint32_t addr = stA + (uint32_t)(row * 128) +
                    (uint32_t)((((kc * 2 + a_u) ^ (row & 7))) << 4);
                ldmatrix_x4(af[mt][0], af[mt][1], af[mt][2], af[mt][3], addr);
            }
            uint32_t bf[4][2];
            #pragma unroll
            for (int nb = 0; nb < 2; nb++) {
                const int row = warpN * 32 + nb * 16 + b_row;
                const uint32_t addr = stB + (uint32_t)(row * 128) +
                    (uint32_t)((((kc * 2 + b_u) ^ (row & 7))) << 4);
                uint32_t r0, r1, r2, r3;
                ldmatrix_x4(r0, r1, r2, r3, addr);
                bf[nb * 2 + 0][0] = r0; bf[nb * 2 + 0][1] = r1;
                bf[nb * 2 + 1][0] = r2; bf[nb * 2 + 1][1] = r3;
            }
            #pragma unroll
            for (int mt = 0; mt < 2; mt++)
                #pragma unroll
                for (int nt = 0; nt < 4; nt++)
                    mma_tf32(acc[mt][nt][0], acc[mt][nt][1],
                             acc[mt][nt][2], acc[mt][nt][3],
                             af[mt][0], af[mt][1], af[mt][2], af[mt][3],
                             bf[nt][0], bf[nt][1]);
        }
    }

    // epilogue
    const int g = lane >> 2;
    const int t = lane & 3;
    float bb[4][2];
    #pragma unroll
    for (int nt = 0; nt < 4; nt++) {
        const int col = colN + warpN * 32 + nt * 8 + 2 * t;
        bb[nt][0] = __ldg(bias + col);
        bb[nt][1] = __ldg(bias + col + 1);
    }
    if (mode == 2) {
        // transposed store (V): dst[(b*1024 + n)*2048 + s], rounded
        #pragma unroll
        for (int mt = 0; mt < 2; mt++) {
            const int r0_ = rowM + warpM * 32 + mt * 16 + g;
            const int b0i = r0_ >> 11, s0 = r0_ & 2047;
            const int b1i = (r0_ + 8) >> 11, s1 = (r0_ + 8) & 2047;
            #pragma unroll
            for (int nt = 0; nt < 4; nt++) {
                const int col = colN + warpN * 32 + nt * 8 + 2 * t;
                C[((size_t)(b0i * 1024 + col))     * 2048 + s0] = to_tf32(acc[mt][nt][0] + bb[nt][0]);
                C[((size_t)(b0i * 1024 + col + 1)) * 2048 + s0] = to_tf32(acc[mt][nt][1] + bb[nt][1]);
                C[((size_t)(b1i * 1024 + col))     * 2048 + s1] = to_tf32(acc[mt][nt][2] + bb[nt][0]);
                C[((size_t)(b1i * 1024 + col + 1)) * 2048 + s1] = to_tf32(acc[mt][nt][3] + bb[nt][1]);
            }
        }
    } else {
        #pragma unroll
        for (int mt = 0; mt < 2; mt++) {
            const int r0_ = rowM + warpM * 32 + mt * 16 + g;
            #pragma unroll
            for (int nt = 0; nt < 4; nt++) {
                const int col = colN + warpN * 32 + nt * 8 + 2 * t;
                float2 v0, v1;
                v0.x = acc[mt][nt][0] + bb[nt][0];
                v0.y = acc[mt][nt][1] + bb[nt][1];
                v1.x = acc[mt][nt][2] + bb[nt][0];
                v1.y = acc[mt][nt][3] + bb[nt][1];
                if (mode == 1) {
                    v0.x = to_tf32(v0.x); v0.y = to_tf32(v0.y);
                    v1.x = to_tf32(v1.x); v1.y = to_tf32(v1.y);
                }
                *(float2*)(C + (size_t)r0_ * N + col)       = v0;
                *(float2*)(C + (size_t)(r0_ + 8) * N + col) = v1;
            }
        }
    }
}

// ---------------------------------------------------------------------------
// Tensor-core flash attention (tf32 mma.sync), cp.async tile loads.
// q pre-rounded tf32 [B,S,HID]; k pre-rounded [B,S,HID];
// v pre-rounded TRANSPOSED [(b*16+h)*64+d][s].
// ---------------------------------------------------------------------------
#define BQ 128
#define BK 64
#define APITCH 68
#define SK_OFF   (128 * APITCH)
#define SVT_OFF  (SK_OFF + BK * APITCH)
#define SP_OFF   (SVT_OFF + HD_ * APITCH)
#define ATTN_SMEM ((SP_OFF + 128 * APITCH) * 4)    // 104448 B

__global__ void __launch_bounds__(256, 2)
attn_tc(const float* __restrict__ Q, const float* __restrict__ Kg_,
        const float* __restrict__ Vt_, float* __restrict__ O)
{
    extern __shared__ float smf[];
    float* sQ  = smf;

    const int tid  = threadIdx.x;
    const int wid  = tid >> 5;
    const int lane = tid & 31;
    const int g    = lane >> 2;
    const int t    = lane & 3;
    const int bh   = blockIdx.y;
    const int b    = bh / NH_;
    const int h    = bh % NH_;
    const int q0   = blockIdx.x * BQ;

    float* myP = smf + SP_OFF + wid * 16 * APITCH;

    const uint32_t uQ  = smem_u32(sQ);
    const uint32_t uK  = uQ + SK_OFF * 4;
    const uint32_t uVt = uQ + SVT_OFF * 4;
    const uint32_t uP  = smem_u32(myP);

    const int a_row = ((lane >> 3) & 1) * 8 + (lane & 7);
    const int a_kq  = ((lane >> 4) & 1) * 4;
    const int b_row = ((lane >> 4) & 1) * 8 + (lane & 7);
    const int b_kq  = ((lane >> 3) & 1) * 4;

    // ---- stage Q (pre-rounded; x0.125 exact in tf32) ----
    {
        const int r  = tid >> 1;
        const int c0 = (tid & 1) * 32;
        const float* src = Q + (size_t)(b * S_ + q0 + r) * HID_ + h * HD_ + c0;
        float* dst = sQ + r * APITCH + c0;
        #pragma unroll
        for (int j = 0; j < 8; j++) {
            float4 v4 = *(const float4*)(src + 4 * j);
            dst[4 * j + 0] = v4.x * 0.125f;
            dst[4 * j + 1] = v4.y * 0.125f;
            dst[4 * j + 2] = v4.z * 0.125f;
            dst[4 * j + 3] = v4.w * 0.125f;
        }
    }

    float o[8][4];
    #pragma unroll
    for (int nt = 0; nt < 8; nt++)
        #pragma unroll
        for (int q = 0; q < 4; q++) o[nt][q] = 0.0f;
    float m0 = -1e30f, m1 = -1e30f, l0 = 0.0f, l1 = 0.0f;

    const float* Kg  = Kg_ + (size_t)(b * S_) * HID_ + h * HD_;
    const float* Vtg = Vt_ + (size_t)(b * 1024 + h * 64) * 2048;

    // cp.async tile-load mapping: r = row 0..63, 4 consecutive 16B units
    const int lr = tid >> 2;            // 0..63
    const int lu = (tid & 3) * 4;       // unit base 0,4,8,12

    __syncthreads();

    for (int kt = 0; kt < S_; kt += BK) {
        // ---- async load K tile [64 keys][64 d] and Vt tile [64 d][64 keys] ----
        {
            const uint32_t dk = uK  + (uint32_t)(lr * (APITCH * 4) + lu * 16);
            const uint32_t dv = uVt + (uint32_t)(lr * (APITCH * 4) + lu * 16);
            const float* ks = Kg  + (size_t)(kt + lr) * HID_ + lu * 4;
            const float* vs = Vtg + (size_t)lr * 2048 + kt + lu * 4;
            #pragma unroll
            for (int i = 0; i < 4; i++) {
                CPA16(dk + i * 16, ks + i * 4);
                CPA16(dv + i * 16, vs + i * 4);
            }
            CPA_COMMIT();
            CPA_WAIT0();
        }
        __syncthreads();

        // ---- S = Q @ K^T ----
        float s[8][4];
        #pragma unroll
        for (int nt = 0; nt < 8; nt++)
            #pragma unroll
            for (int q = 0; q < 4; q++) s[nt][q] = 0.0f;

        #pragma unroll
        for (int kc = 0; kc < 8; kc++) {
            uint32_t qf[4];
            ldmatrix_x4(qf[0], qf[1], qf[2], qf[3],
                uQ + (uint32_t)(((wid * 16 + a_row) * APITCH + kc * 8 + a_kq) * 4));
            uint32_t bf[8][2];
            #pragma unroll
            for (int nb = 0; nb < 4; nb++) {
                uint32_t r0, r1, r2, r3;
                ldmatrix_x4(r0, r1, r2, r3,
                    uK + (uint32_t)(((nb * 16 + b_row) * APITCH + kc * 8 + b_kq) * 4));
                bf[nb * 2 + 0][0] = r0; bf[nb * 2 + 0][1] = r1;
                bf[nb * 2 + 1][0] = r2; bf[nb * 2 + 1][1] = r3;
            }
            #pragma unroll
            for (int nt = 0; nt < 8; nt++)
                mma_tf32(s[nt][0], s[nt][1], s[nt][2], s[nt][3],
                         qf[0], qf[1], qf[2], qf[3], bf[nt][0], bf[nt][1]);
        }

        // ---- online softmax ----
        float mx0 = -1e30f, mx1 = -1e30f;
        #pragma unroll
        for (int nt = 0; nt < 8; nt++) {
            mx0 = fmaxf(mx0, fmaxf(s[nt][0], s[nt][1]));
            mx1 = fmaxf(mx1, fmaxf(s[nt][2], s[nt][3]));
        }
        mx0 = quad_max(mx0); mx1 = quad_max(mx1);
        const float mn0 = fmaxf(m0, mx0);
        const float mn1 = fmaxf(m1, mx1);
        const float c0r = __expf(m0 - mn0);
        const float c1r = __expf(m1 - mn1);
        m0 = mn0; m1 = mn1;

        float sum0 = 0.0f, sum1 = 0.0f;
        #pragma unroll
        for (int nt = 0; nt < 8; nt++) {
            float p0 = __expf(s[nt][0] - mn0);
            float p1 = __expf(s[nt][1] - mn0);
            float p2 = __expf(s[nt][2] - mn1);
            float p3 = __expf(s[nt][3] - mn1);
            sum0 += p0 + p1;
            sum1 += p2 + p3;
            o[nt][0] *= c0r; o[nt][1] *= c0r;
            o[nt][2] *= c1r; o[nt][3] *= c1r;
            float2 lo, hi;
            lo.x = to_tf32(p0); lo.y = to_tf32(p1);
            hi.x = to_tf32(p2); hi.y = to_tf32(p3);
            *(float2*)(myP + g * APITCH + nt * 8 + 2 * t)       = lo;
            *(float2*)(myP + (g + 8) * APITCH + nt * 8 + 2 * t) = hi;
        }
        sum0 = quad_sum(sum0); sum1 = quad_sum(sum1);
        l0 = l0 * c0r + sum0;
        l1 = l1 * c1r + sum1;
        __syncwarp();

        // ---- O += P @ V ----
        #pragma unroll
        for (int kc = 0; kc < 8; kc++) {
            uint32_t af[4];
            ldmatrix_x4(af[0], af[1], af[2], af[3],
                uP + (uint32_t)((a_row * APITCH + kc * 8 + a_kq) * 4));
            uint32_t vf[8][2];
            #pragma unroll
            for (int nb = 0; nb < 4; nb++) {
                uint32_t r0, r1, r2, r3;
                ldmatrix_x4(r0, r1, r2, r3,
                    uVt + (uint32_t)(((nb * 16 + b_row) * APITCH + kc * 8 + b_kq) * 4));
                vf[nb * 2 + 0][0] = r0; vf[nb * 2 + 0][1] = r1;
                vf[nb * 2 + 1][0] = r2; vf[nb * 2 + 1][1] = r3;
            }
            #pragma unroll
            for (int nt = 0; nt < 8; nt++)
                mma_tf32(o[nt][0], o[nt][1], o[nt][2], o[nt][3],
                         af[0], af[1], af[2], af[3], vf[nt][0], vf[nt][1]);
        }
        __syncthreads();
    }

    // ---- normalize + store tf32-rounded ([B,S,HID] concat-heads) ----
    const float inv0 = 1.0f / l0;
    const float inv1 = 1.0f / l1;
    const size_t row0 = (size_t)(b * S_ + q0 + wid * 16 + g) * HID_ + h * HD_;
    #pragma unroll
    for (int nt = 0; nt < 8; nt++) {
        float2 v0, v1;
        v0.x = to_tf32(o[nt][0] * inv0); v0.y = to_tf32(o[nt][1] * inv0);
        v1.x = to_tf32(o[nt][2] * inv1); v1.y = to_tf32(o[nt][3] * inv1);
        *(float2*)(O + row0 + nt * 8 + 2 * t)              = v0;
        *(float2*)(O + row0 + 8 * HID_ + nt * 8 + 2 * t)   = v1;
    }
}

// ---------------------------------------------------------------------------
// Launch
// ---------------------------------------------------------------------------
extern "C" void kernel_launch(void* const* d_in, const int* in_sizes, int n_in,
                              void* d_out, int out_size)
{
    const float* x  = (const float*)d_in[0];
    const float* Wq = (const float*)d_in[1];
    const float* bq = (const float*)d_in[2];
    const float* Wk = (const float*)d_in[3];
    const float* bk = (const float*)d_in[4];
    const float* Wv = (const float*)d_in[5];
    const float* bv = (const float*)d_in[6];
    const float* Wo = (const float*)d_in[7];
    const float* bo = (const float*)d_in[8];
    float* out = (float*)d_out;

    float *qp, *kp, *vp, *ap, *xt, *wt, *wo;
    cudaGetSymbolAddress((void**)&qp, g_q);
    cudaGetSymbolAddress((void**)&kp, g_k);
    cudaGetSymbolAddress((void**)&vp, g_v);
    cudaGetSymbolAddress((void**)&ap, g_attn);
    cudaGetSymbolAddress((void**)&xt, g_xt);
    cudaGetSymbolAddress((void**)&wt, g_wt);
    cudaGetSymbolAddress((void**)&wo, g_wo);

    cudaFuncSetAttribute(gemm_tc, cudaFuncAttributeMaxDynamicSharedMemorySize,
                         GEMM_SMEM);
    cudaFuncSetAttribute(attn_tc, cudaFuncAttributeMaxDynamicSharedMemorySize,
                         ATTN_SMEM);

    // 0) pre-round inputs/weights to tf32 (RNA)
    {
        const int NX4 = MTOT * HID_ / 4;
        const int NW4 = HID_ * HID_ / 4;
        round_vec<<<NX4 / 256, 256>>>(x,  xt, NX4);
        round_vec<<<NW4 / 256, 256>>>(Wq, wt,                   NW4);
        round_vec<<<NW4 / 256, 256>>>(Wk, wt + HID_ * HID_,     NW4);
        round_vec<<<NW4 / 256, 256>>>(Wv, wt + 2 * HID_ * HID_, NW4);
        round_vec<<<NW4 / 256, 256>>>(Wo, wo, NW4);
    }

    // 1) fused QKV projections (V written transposed per head)
    {
        dim3 grid(HID_ / 128, MTOT / 128, 3);
        gemm_tc<<<grid, 512, GEMM_SMEM>>>(xt, wt, wt + HID_ * HID_,
                                          wt + 2 * HID_ * HID_,
                                          bq, bk, bv, qp, kp, vp,
                                          MTOT, HID_, HID_, 1, 1, 2);
    }

    // 2) attention
    {
        dim3 grid(S_ / BQ, B_ * NH_);
        attn_tc<<<grid, 256, ATTN_SMEM>>>(qp, kp, vp, ap);
    }

    // 3) output projection
    {
        dim3 grid(HID_ / 128, MTOT / 128, 1);
        gemm_tc<<<grid, 512, GEMM_SMEM>>>(ap, wo, wo, wo, bo, bo, bo,
                                          out, out, out, MTOT, HID_, HID_,
                                          0, 0, 0);
    }
}

// round 7
// speedup vs baseline: 3.3785x; 1.0577x over previous
#include <cuda_runtime.h>
#include <cstdint>
#include <math.h>

#define B_   2
#define S_   2048
#define HID_ 1024
#define NH_  16
#define HD_  64
#define MTOT (B_ * S_)   // 4096

// ---------------------------------------------------------------------------
// Scratch buffers (no cudaMalloc allowed)
// g_v holds V TRANSPOSED per (b,h): layout [(b*16+h)*64 + d][s], pitch S_.
// ---------------------------------------------------------------------------
__device__ float g_q[MTOT * HID_];
__device__ float g_v[MTOT * HID_];
__device__ float g_k[MTOT * HID_];
__device__ float g_attn[MTOT * HID_];
__device__ float g_xt[MTOT * HID_];          // tf32-rounded x
__device__ float g_wt[3 * HID_ * HID_];      // tf32-rounded Wq,Wk,Wv
__device__ float g_wo[HID_ * HID_];          // tf32-rounded Wo

// ---------------------------------------------------------------------------
// Helpers
// ---------------------------------------------------------------------------
__device__ __forceinline__ uint32_t smem_u32(const void* p) {
    uint32_t a;
    asm("{ .reg .u64 t; cvta.to.shared.u64 t, %1; cvt.u32.u64 %0, t; }"
        : "=r"(a) : "l"(p));
    return a;
}

__device__ __forceinline__ float to_tf32(float x) {
    uint32_t o;
    asm("cvt.rna.tf32.f32 %0, %1;" : "=r"(o) : "f"(x));
    return __uint_as_float(o);
}

__device__ __forceinline__ void ldmatrix_x4(uint32_t& r0, uint32_t& r1,
                                            uint32_t& r2, uint32_t& r3,
                                            uint32_t addr) {
    asm volatile("ldmatrix.sync.aligned.m8n8.x4.shared.b16 {%0,%1,%2,%3}, [%4];"
                 : "=r"(r0), "=r"(r1), "=r"(r2), "=r"(r3) : "r"(addr));
}

__device__ __forceinline__ void mma_tf32(float& c0, float& c1, float& c2, float& c3,
                                         uint32_t a0, uint32_t a1, uint32_t a2,
                                         uint32_t a3, uint32_t b0, uint32_t b1) {
    asm volatile(
        "mma.sync.aligned.m16n8k8.row.col.f32.tf32.tf32.f32 "
        "{%0,%1,%2,%3}, {%4,%5,%6,%7}, {%8,%9}, {%0,%1,%2,%3};"
        : "+f"(c0), "+f"(c1), "+f"(c2), "+f"(c3)
        : "r"(a0), "r"(a1), "r"(a2), "r"(a3), "r"(b0), "r"(b1));
}

__device__ __forceinline__ float quad_max(float v) {
    v = fmaxf(v, __shfl_xor_sync(0xffffffffu, v, 1));
    v = fmaxf(v, __shfl_xor_sync(0xffffffffu, v, 2));
    return v;
}
__device__ __forceinline__ float quad_sum(float v) {
    v += __shfl_xor_sync(0xffffffffu, v, 1);
    v += __shfl_xor_sync(0xffffffffu, v, 2);
    return v;
}

#define CPA16(dst, src) \
    asm volatile("cp.async.cg.shared.global [%0], [%1], 16;" \
                 :: "r"(dst), "l"(src) : "memory")
#define CPA_COMMIT() asm volatile("cp.async.commit_group;" ::: "memory")
#define CPA_WAIT1()  asm volatile("cp.async.wait_group 1;" ::: "memory")
#define CPA_WAIT0()  asm volatile("cp.async.wait_group 0;" ::: "memory")

// ---------------------------------------------------------------------------
// tf32 pre-rounding passes
// ---------------------------------------------------------------------------
__global__ void __launch_bounds__(256)
round_vec(const float* __restrict__ in, float* __restrict__ out, int n4)
{
    int i = blockIdx.x * 256 + threadIdx.x;
    if (i < n4) {
        float4 v = ((const float4*)in)[i];
        float4 o;
        o.x = to_tf32(v.x); o.y = to_tf32(v.y);
        o.z = to_tf32(v.z); o.w = to_tf32(v.w);
        ((float4*)out)[i] = o;
    }
}

__global__ void __launch_bounds__(256)
round_w4(const float* __restrict__ w0, const float* __restrict__ w1,
         const float* __restrict__ w2, const float* __restrict__ w3,
         float* __restrict__ o0, float* __restrict__ o1,
         float* __restrict__ o2, float* __restrict__ o3, int n4)
{
    const float* in; float* out;
    if (blockIdx.z == 0)      { in = w0; out = o0; }
    else if (blockIdx.z == 1) { in = w1; out = o1; }
    else if (blockIdx.z == 2) { in = w2; out = o2; }
    else                      { in = w3; out = o3; }
    int i = blockIdx.x * 256 + threadIdx.x;
    if (i < n4) {
        float4 v = ((const float4*)in)[i];
        float4 o;
        o.x = to_tf32(v.x); o.y = to_tf32(v.y);
        o.z = to_tf32(v.z); o.w = to_tf32(v.w);
        ((float4*)out)[i] = o;
    }
}

// ---------------------------------------------------------------------------
// tf32 mma.sync GEMM, cp.async 3-stage pipeline, 512 threads (16 warps 4x4),
// CTA tile 128x128x32, warp tile 32x32.   (unchanged from round 6)
// ---------------------------------------------------------------------------
#define STAGE_BYTES 32768
#define GEMM_SMEM (3 * STAGE_BYTES)

__global__ void __launch_bounds__(512)
gemm_tc(const float* __restrict__ A,
        const float* __restrict__ W0, const float* __restrict__ W1,
        const float* __restrict__ W2,
        const float* __restrict__ b0_, const float* __restrict__ b1_,
        const float* __restrict__ b2_,
        float* __restrict__ C0, float* __restrict__ C1, float* __restrict__ C2,
        int M, int N, int K, int mode0, int mode1, int mode2)
{
    extern __shared__ char smc[];
    const uint32_t sbase = smem_u32(smc);
    const int tid  = threadIdx.x;
    const int wid  = tid >> 5;
    const int lane = tid & 31;
    const int warpM = wid & 3;
    const int warpN = wid >> 2;

    const float* W; const float* bias; float* C; int mode;
    if (blockIdx.z == 0)      { W = W0; bias = b0_; C = C0; mode = mode0; }
    else if (blockIdx.z == 1) { W = W1; bias = b1_; C = C1; mode = mode1; }
    else                      { W = W2; bias = b2_; C = C2; mode = mode2; }

    const int rowM = blockIdx.y * 128;
    const int colN = blockIdx.x * 128;
    const float* Ag = A + (size_t)rowM * K;
    const float* Wg = W + (size_t)colN * K;

    const int cr = tid >> 2;
    const int cu = (tid & 3) * 2;
    const float* agr = Ag + (size_t)cr * K;
    const float* wgr = Wg + (size_t)cr * K;

    const int a_row = ((lane >> 3) & 1) * 8 + (lane & 7);
    const int a_u   = (lane >> 4) & 1;
    const int b_row = ((lane >> 4) & 1) * 8 + (lane & 7);
    const int b_u   = (lane >> 3) & 1;

    float acc[2][4][4];
    #pragma unroll
    for (int mt = 0; mt < 2; mt++)
        #pragma unroll
        for (int nt = 0; nt < 4; nt++)
            #pragma unroll
            for (int q = 0; q < 4; q++) acc[mt][nt][q] = 0.0f;

    const int NC = K / 32;

    #pragma unroll
    for (int s = 0; s < 2; s++) {
        const uint32_t sa = sbase + s * STAGE_BYTES + cr * 128;
        const float* ac = agr + s * 32;
        const float* wc = wgr + s * 32;
        #pragma unroll
        for (int i = 0; i < 2; i++) {
            const int u = cu + i;
            const uint32_t off = (uint32_t)((u ^ (cr & 7)) << 4);
            CPA16(sa + off,         ac + u * 4);
            CPA16(sa + 16384 + off, wc + u * 4);
        }
        CPA_COMMIT();
    }

    for (int c = 0; c < NC; c++) {
        const int buf = c % 3;
        CPA_WAIT1();
        __syncthreads();

        if (c + 2 < NC) {
            const int s = (c + 2) % 3;
            const uint32_t sa = sbase + s * STAGE_BYTES + cr * 128;
            const float* ac = agr + (c + 2) * 32;
            const float* wc = wgr + (c + 2) * 32;
            #pragma unroll
            for (int i = 0; i < 2; i++) {
                const int u = cu + i;
                const uint32_t off = (uint32_t)((u ^ (cr & 7)) << 4);
                CPA16(sa + off,         ac + u * 4);
                CPA16(sa + 16384 + off, wc + u * 4);
            }
        }
        CPA_COMMIT();

        const uint32_t stA = sbase + buf * STAGE_BYTES;
        const uint32_t stB = stA + 16384;
        #pragma unroll
        for (int kc = 0; kc < 4; kc++) {
            uint32_t af[2][4];
            #pragma unroll
            for (int mt = 0; mt < 2; mt++) {
                const int row = warpM * 32 + mt * 16 + a_row;
                const uint32_t addr = stA + (uint32_t)(row * 128) +
                    (uint32_t)((((kc * 2 + a_u) ^ (row & 7))) << 4);
                ldmatrix_x4(af[mt][0], af[mt][1], af[mt][2], af[mt][3], addr);
            }
            uint32_t bf[4][2];
            #pragma unroll
            for (int nb = 0; nb < 2; nb++) {
                const int row = warpN * 32 + nb * 16 + b_row;
                const uint32_t addr = stB + (uint32_t)(row * 128) +
                    (uint32_t)((((kc * 2 + b_u) ^ (row & 7))) << 4);
                uint32_t r0, r1, r2, r3;
                ldmatrix_x4(r0, r1, r2, r3, addr);
                bf[nb * 2 + 0][0] = r0; bf[nb * 2 + 0][1] = r1;
                bf[nb * 2 + 1][0] = r2; bf[nb * 2 + 1][1] = r3;
            }
            #pragma unroll
            for (int mt = 0; mt < 2; mt++)
                #pragma unroll
                for (int nt = 0; nt < 4; nt++)
                    mma_tf32(acc[mt][nt][0], acc[mt][nt][1],
                             acc[mt][nt][2], acc[mt][nt][3],
                             af[mt][0], af[mt][1], af[mt][2], af[mt][3],
                             bf[nt][0], bf[nt][1]);
        }
    }

    const int g = lane >> 2;
    const int t = lane & 3;
    float bb[4][2];
    #pragma unroll
    for (int nt = 0; nt < 4; nt++) {
        const int col = colN + warpN * 32 + nt * 8 + 2 * t;
        bb[nt][0] = __ldg(bias + col);
        bb[nt][1] = __ldg(bias + col + 1);
    }
    if (mode == 2) {
        #pragma unroll
        for (int mt = 0; mt < 2; mt++) {
            const int r0_ = rowM + warpM * 32 + mt * 16 + g;
            const int b0i = r0_ >> 11, s0 = r0_ & 2047;
            const int b1i = (r0_ + 8) >> 11, s1 = (r0_ + 8) & 2047;
            #pragma unroll
            for (int nt = 0; nt < 4; nt++) {
                const int col = colN + warpN * 32 + nt * 8 + 2 * t;
                C[((size_t)(b0i * 1024 + col))     * 2048 + s0] = to_tf32(acc[mt][nt][0] + bb[nt][0]);
                C[((size_t)(b0i * 1024 + col + 1)) * 2048 + s0] = to_tf32(acc[mt][nt][1] + bb[nt][1]);
                C[((size_t)(b1i * 1024 + col))     * 2048 + s1] = to_tf32(acc[mt][nt][2] + bb[nt][0]);
                C[((size_t)(b1i * 1024 + col + 1)) * 2048 + s1] = to_tf32(acc[mt][nt][3] + bb[nt][1]);
            }
        }
    } else {
        #pragma unroll
        for (int mt = 0; mt < 2; mt++) {
            const int r0_ = rowM + warpM * 32 + mt * 16 + g;
            #pragma unroll
            for (int nt = 0; nt < 4; nt++) {
                const int col = colN + warpN * 32 + nt * 8 + 2 * t;
                float2 v0, v1;
                v0.x = acc[mt][nt][0] + bb[nt][0];
                v0.y = acc[mt][nt][1] + bb[nt][1];
                v1.x = acc[mt][nt][2] + bb[nt][0];
                v1.y = acc[mt][nt][3] + bb[nt][1];
                if (mode == 1) {
                    v0.x = to_tf32(v0.x); v0.y = to_tf32(v0.y);
                    v1.x = to_tf32(v1.x); v1.y = to_tf32(v1.y);
                }
                *(float2*)(C + (size_t)r0_ * N + col)       = v0;
                *(float2*)(C + (size_t)(r0_ + 8) * N + col) = v1;
            }
        }
    }
}

// ---------------------------------------------------------------------------
// Tensor-core flash attention, double-buffered cp.async K/V pipeline.
// Q fragments held in registers (loaded once). smem:
//   KV buf0 [0, 8704), KV buf1 [8704, 17408), sP [17408, 26112) floats.
//   Each KV buf: sK 64x68 then sVt 64x68. Q staged initially in buf1.
// ---------------------------------------------------------------------------
#define BQ 128
#define BK 64
#define APITCH 68
#define KVBUF_F (2 * BK * APITCH)                  // 8704 floats
#define SP_OFF  (2 * KVBUF_F)                      // 17408 floats
#define ATTN_SMEM ((SP_OFF + 128 * APITCH) * 4)    // 104448 B

__global__ void __launch_bounds__(256, 2)
attn_tc(const float* __restrict__ Q, const float* __restrict__ Kg_,
        const float* __restrict__ Vt_, float* __restrict__ O)
{
    extern __shared__ float smf[];

    const int tid  = threadIdx.x;
    const int wid  = tid >> 5;
    const int lane = tid & 31;
    const int g    = lane >> 2;
    const int t    = lane & 3;
    const int bh   = blockIdx.y;
    const int b    = bh / NH_;
    const int h    = bh % NH_;
    const int q0   = blockIdx.x * BQ;

    float* myP = smf + SP_OFF + wid * 16 * APITCH;

    const uint32_t uB0 = smem_u32(smf);
    const uint32_t uB1 = uB0 + KVBUF_F * 4;
    const uint32_t uP  = smem_u32(myP);

    const int a_row = ((lane >> 3) & 1) * 8 + (lane & 7);
    const int a_kq  = ((lane >> 4) & 1) * 4;
    const int b_row = ((lane >> 4) & 1) * 8 + (lane & 7);
    const int b_kq  = ((lane >> 3) & 1) * 4;

    const float* Kg  = Kg_ + (size_t)(b * S_) * HID_ + h * HD_;
    const float* Vtg = Vt_ + (size_t)(b * 1024 + h * 64) * 2048;

    // cp.async tile-load mapping
    const int lr = tid >> 2;            // 0..63
    const int lu = (tid & 3) * 4;       // 16B-unit base

    // ---- issue tile 0 into buf0 immediately ----
    {
        const uint32_t dk = uB0 + (uint32_t)(lr * (APITCH * 4) + lu * 16);
        const uint32_t dv = dk + (uint32_t)(BK * APITCH * 4);
        const float* ks = Kg  + (size_t)lr * HID_ + lu * 4;
        const float* vs = Vtg + (size_t)lr * 2048 + lu * 4;
        #pragma unroll
        for (int i = 0; i < 4; i++) {
            CPA16(dk + i * 16, ks + i * 4);
            CPA16(dv + i * 16, vs + i * 4);
        }
        CPA_COMMIT();
    }

    // ---- stage Q into buf1 region, extract fragments to registers ----
    {
        const int r  = tid >> 1;
        const int c0 = (tid & 1) * 32;
        const float* src = Q + (size_t)(b * S_ + q0 + r) * HID_ + h * HD_ + c0;
        float* dst = smf + KVBUF_F + r * APITCH + c0;
        #pragma unroll
        for (int j = 0; j < 8; j++) {
            float4 v4 = *(const float4*)(src + 4 * j);
            dst[4 * j + 0] = v4.x * 0.125f;
            dst[4 * j + 1] = v4.y * 0.125f;
            dst[4 * j + 2] = v4.z * 0.125f;
            dst[4 * j + 3] = v4.w * 0.125f;
        }
    }
    __syncthreads();

    uint32_t qf[8][4];
    #pragma unroll
    for (int kc = 0; kc < 8; kc++)
        ldmatrix_x4(qf[kc][0], qf[kc][1], qf[kc][2], qf[kc][3],
            uB1 + (uint32_t)(((wid * 16 + a_row) * APITCH + kc * 8 + a_kq) * 4));
    __syncthreads();   // everyone done reading buf1 (Q staging)

    float o[8][4];
    #pragma unroll
    for (int nt = 0; nt < 8; nt++)
        #pragma unroll
        for (int q = 0; q < 4; q++) o[nt][q] = 0.0f;
    float m0 = -1e30f, m1 = -1e30f, l0 = 0.0f, l1 = 0.0f;

    const int NT = S_ / BK;   // 32

    for (int kt = 0; kt < NT; kt++) {
        const uint32_t uKb  = (kt & 1) ? uB1 : uB0;
        const uint32_t uVtb = uKb + (uint32_t)(BK * APITCH * 4);

        // issue next tile into the other buffer
        if (kt + 1 < NT) {
            const uint32_t dst = (kt & 1) ? uB0 : uB1;
            const uint32_t dk = dst + (uint32_t)(lr * (APITCH * 4) + lu * 16);
            const uint32_t dv = dk + (uint32_t)(BK * APITCH * 4);
            const float* ks = Kg  + (size_t)((kt + 1) * BK + lr) * HID_ + lu * 4;
            const float* vs = Vtg + (size_t)lr * 2048 + (kt + 1) * BK + lu * 4;
            #pragma unroll
            for (int i = 0; i < 4; i++) {
                CPA16(dk + i * 16, ks + i * 4);
                CPA16(dv + i * 16, vs + i * 4);
            }
            CPA_COMMIT();
            CPA_WAIT1();
        } else {
            CPA_WAIT0();
        }
        __syncthreads();

        // ---- S = Q @ K^T (Q fragments in registers) ----
        float s[8][4];
        #pragma unroll
        for (int nt = 0; nt < 8; nt++)
            #pragma unroll
            for (int q = 0; q < 4; q++) s[nt][q] = 0.0f;

        #pragma unroll
        for (int kc = 0; kc < 8; kc++) {
            uint32_t bf[8][2];
            #pragma unroll
            for (int nb = 0; nb < 4; nb++) {
                uint32_t r0, r1, r2, r3;
                ldmatrix_x4(r0, r1, r2, r3,
                    uKb + (uint32_t)(((nb * 16 + b_row) * APITCH + kc * 8 + b_kq) * 4));
                bf[nb * 2 + 0][0] = r0; bf[nb * 2 + 0][1] = r1;
                bf[nb * 2 + 1][0] = r2; bf[nb * 2 + 1][1] = r3;
            }
            #pragma unroll
            for (int nt = 0; nt < 8; nt++)
                mma_tf32(s[nt][0], s[nt][1], s[nt][2], s[nt][3],
                         qf[kc][0], qf[kc][1], qf[kc][2], qf[kc][3],
                         bf[nt][0], bf[nt][1]);
        }

        // ---- online softmax ----
        float mx0 = -1e30f, mx1 = -1e30f;
        #pragma unroll
        for (int nt = 0; nt < 8; nt++) {
            mx0 = fmaxf(mx0, fmaxf(s[nt][0], s[nt][1]));
            mx1 = fmaxf(mx1, fmaxf(s[nt][2], s[nt][3]));
        }
        mx0 = quad_max(mx0); mx1 = quad_max(mx1);
        const float mn0 = fmaxf(m0, mx0);
        const float mn1 = fmaxf(m1, mx1);
        const float c0r = __expf(m0 - mn0);
        const float c1r = __expf(m1 - mn1);
        m0 = mn0; m1 = mn1;

        float sum0 = 0.0f, sum1 = 0.0f;
        #pragma unroll
        for (int nt = 0; nt < 8; nt++) {
            float p0 = __expf(s[nt][0] - mn0);
            float p1 = __expf(s[nt][1] - mn0);
            float p2 = __expf(s[nt][2] - mn1);
            float p3 = __expf(s[nt][3] - mn1);
            sum0 += p0 + p1;
            sum1 += p2 + p3;
            o[nt][0] *= c0r; o[nt][1] *= c0r;
            o[nt][2] *= c1r; o[nt][3] *= c1r;
            float2 lo, hi;
            lo.x = to_tf32(p0); lo.y = to_tf32(p1);
            hi.x = to_tf32(p2); hi.y = to_tf32(p3);
            *(float2*)(myP + g * APITCH + nt * 8 + 2 * t)       = lo;
            *(float2*)(myP + (g + 8) * APITCH + nt * 8 + 2 * t) = hi;
        }
        sum0 = quad_sum(sum0); sum1 = quad_sum(sum1);
        l0 = l0 * c0r + sum0;
        l1 = l1 * c1r + sum1;
        __syncwarp();

        // ---- O += P @ V ----
        #pragma unroll
        for (int kc = 0; kc < 8; kc++) {
            uint32_t af[4];
            ldmatrix_x4(af[0], af[1], af[2], af[3],
                uP + (uint32_t)((a_row * APITCH + kc * 8 + a_kq) * 4));
            uint32_t vf[8][2];
            #pragma unroll
            for (int nb = 0; nb < 4; nb++) {
                uint32_t r0, r1, r2, r3;
                ldmatrix_x4(r0, r1, r2, r3,
                    uVtb + (uint32_t)(((nb * 16 + b_row) * APITCH + kc * 8 + b_kq) * 4));
                vf[nb * 2 + 0][0] = r0; vf[nb * 2 + 0][1] = r1;
                vf[nb * 2 + 1][0] = r2; vf[nb * 2 + 1][1] = r3;
            }
            #pragma unroll
            for (int nt = 0; nt < 8; nt++)
                mma_tf32(o[nt][0], o[nt][1], o[nt][2], o[nt][3],
                         af[0], af[1], af[2], af[3], vf[nt][0], vf[nt][1]);
        }
        __syncthreads();   // all reads of current buf done before re-issue
    }

    // ---- normalize + store tf32-rounded ----
    const float inv0 = 1.0f / l0;
    const float inv1 = 1.0f / l1;
    const size_t row0 = (size_t)(b * S_ + q0 + wid * 16 + g) * HID_ + h * HD_;
    #pragma unroll
    for (int nt = 0; nt < 8; nt++) {
        float2 v0, v1;
        v0.x = to_tf32(o[nt][0] * inv0); v0.y = to_tf32(o[nt][1] * inv0);
        v1.x = to_tf32(o[nt][2] * inv1); v1.y = to_tf32(o[nt][3] * inv1);
        *(float2*)(O + row0 + nt * 8 + 2 * t)              = v0;
        *(float2*)(O + row0 + 8 * HID_ + nt * 8 + 2 * t)   = v1;
    }
}

// ---------------------------------------------------------------------------
// Launch
// ---------------------------------------------------------------------------
extern "C" void kernel_launch(void* const* d_in, const int* in_sizes, int n_in,
                              void* d_out, int out_size)
{
    const float* x  = (const float*)d_in[0];
    const float* Wq = (const float*)d_in[1];
    const float* bq = (const float*)d_in[2];
    const float* Wk = (const float*)d_in[3];
    const float* bk = (const float*)d_in[4];
    const float* Wv = (const float*)d_in[5];
    const float* bv = (const float*)d_in[6];
    const float* Wo = (const float*)d_in[7];
    const float* bo = (const float*)d_in[8];
    float* out = (float*)d_out;

    float *qp, *kp, *vp, *ap, *xt, *wt, *wo;
    cudaGetSymbolAddress((void**)&qp, g_q);
    cudaGetSymbolAddress((void**)&kp, g_k);
    cudaGetSymbolAddress((void**)&vp, g_v);
    cudaGetSymbolAddress((void**)&ap, g_attn);
    cudaGetSymbolAddress((void**)&xt, g_xt);
    cudaGetSymbolAddress((void**)&wt, g_wt);
    cudaGetSymbolAddress((void**)&wo, g_wo);

    cudaFuncSetAttribute(gemm_tc, cudaFuncAttributeMaxDynamicSharedMemorySize,
                         GEMM_SMEM);
    cudaFuncSetAttribute(attn_tc, cudaFuncAttributeMaxDynamicSharedMemorySize,
                         ATTN_SMEM);

    // 0) pre-round inputs/weights to tf32 (RNA)
    {
        const int NX4 = MTOT * HID_ / 4;
        const int NW4 = HID_ * HID_ / 4;
        round_vec<<<NX4 / 256, 256>>>(x, xt, NX4);
        dim3 wg(NW4 / 256, 1, 4);
        round_w4<<<wg, 256>>>(Wq, Wk, Wv, Wo,
                              wt, wt + HID_ * HID_, wt + 2 * HID_ * HID_, wo,
                              NW4);
    }

    // 1) fused QKV projections (V written transposed per head)
    {
        dim3 grid(HID_ / 128, MTOT / 128, 3);
        gemm_tc<<<grid, 512, GEMM_SMEM>>>(xt, wt, wt + HID_ * HID_,
                                          wt + 2 * HID_ * HID_,
                                          bq, bk, bv, qp, kp, vp,
                                          MTOT, HID_, HID_, 1, 1, 2);
    }

    // 2) attention (double-buffered cp.async pipeline)
    {
        dim3 grid(S_ / BQ, B_ * NH_);
        attn_tc<<<grid, 256, ATTN_SMEM>>>(qp, kp, vp, ap);
    }

    // 3) output projection
    {
        dim3 grid(HID_ / 128, MTOT / 128, 1);
        gemm_tc<<<grid, 512, GEMM_SMEM>>>(ap, wo, wo, wo, bo, bo, bo,
                                          out, out, out, MTOT, HID_, HID_,
                                          0, 0, 0);
    }
}